// round 6
// baseline (speedup 1.0000x reference)
#include <cuda_runtime.h>
#include <cuda_bf16.h>
#include <cstdint>

#define B_    256
#define T_    512
#define IN_   64
#define H_    1024
#define OUT_  128
#define NCTA  128
#define HBUF  (16 * 64 * 2 * 32)      // uint4s per h buffer: [mt][kc][hl][lane]
#define SMEM_BYTES (64 * 4 * 2 * 256 + 4 * 2048)   // B slice: 68 kc x 2048B = 139264

// ---------------- persistent device scratch ------------------------------
__device__ uint4 g_hA[2 * HBUF];                     // ping-pong h, A-frag packed
__device__ uint4 g_xp[(size_t)T_ * 16 * 4 * 2 * 32]; // x, A-frag packed per t
__device__ float g_hf[B_ * H_];                      // final h, plain fp32
__device__ unsigned g_cnt[4];
__device__ volatile unsigned g_gen[4];

// ---------------- helpers -------------------------------------------------
__device__ __forceinline__ uint32_t smem_u32(const void* p) {
    uint32_t a;
    asm("{ .reg .u64 t; cvta.to.shared.u64 t, %1; cvt.u32.u64 %0, t; }"
        : "=r"(a) : "l"(p));
    return a;
}

__device__ __forceinline__ uint32_t pk(float a, float b) {
    __nv_bfloat162 t = __floats2bfloat162_rn(a, b);
    return *reinterpret_cast<uint32_t*>(&t);
}

__device__ __forceinline__ void lds128(uint32_t* r, uint32_t a) {
    asm("ld.shared.v4.b32 {%0,%1,%2,%3}, [%4];"
        : "=r"(r[0]), "=r"(r[1]), "=r"(r[2]), "=r"(r[3]) : "r"(a));
}

__device__ __forceinline__ void mma16816(float* c, const uint32_t* a, const uint32_t* b) {
    asm("mma.sync.aligned.m16n8k16.row.col.f32.bf16.bf16.f32 "
        "{%0,%1,%2,%3}, {%4,%5,%6,%7}, {%8,%9}, {%0,%1,%2,%3};"
        : "+f"(c[0]), "+f"(c[1]), "+f"(c[2]), "+f"(c[3])
        : "r"(a[0]), "r"(a[1]), "r"(a[2]), "r"(a[3]), "r"(b[0]), "r"(b[1]));
}

// barrier over the 32 CTAs of one m-group (batch rows are independent)
__device__ __forceinline__ void group_sync(int g) {
    __syncthreads();
    if (threadIdx.x == 0) {
        __threadfence();
        unsigned gen = g_gen[g];
        if (atomicAdd(&g_cnt[g], 1u) == 31u) {
            atomicExch(&g_cnt[g], 0u);
            __threadfence();
            g_gen[g] = gen + 1u;
        } else {
            while (g_gen[g] == gen) { }
        }
        __threadfence();
    }
    __syncthreads();
}

// ---------------- pack x into A-fragment layout (one-time) ----------------
__global__ void pack_x(const float* __restrict__ x, uint4* __restrict__ xp) {
    int id = blockIdx.x * (blockDim.x >> 5) + (threadIdx.x >> 5);
    int l  = threadIdx.x & 31;
    if (id >= T_ * 16 * 4) return;
    int t = id >> 6, mt = (id >> 2) & 15, kcx = id & 3;
    int b0 = mt * 16 + (l >> 2), b1 = b0 + 8;
    int i0 = kcx * 16 + 2 * (l & 3);
    const float* x0 = x + ((size_t)b0 * T_ + t) * IN_;
    const float* x1 = x + ((size_t)b1 * T_ + t) * IN_;
    float v00 = x0[i0], v01 = x0[i0 + 1], v02 = x0[i0 + 8], v03 = x0[i0 + 9];
    float v10 = x1[i0], v11 = x1[i0 + 1], v12 = x1[i0 + 8], v13 = x1[i0 + 9];
    uint4 hi4, lo4;
    hi4.x = pk(v00, v01); hi4.y = pk(v10, v11);
    hi4.z = pk(v02, v03); hi4.w = pk(v12, v13);
    float r00 = v00 - __bfloat162float(__float2bfloat16(v00));
    float r01 = v01 - __bfloat162float(__float2bfloat16(v01));
    float r02 = v02 - __bfloat162float(__float2bfloat16(v02));
    float r03 = v03 - __bfloat162float(__float2bfloat16(v03));
    float r10 = v10 - __bfloat162float(__float2bfloat16(v10));
    float r11 = v11 - __bfloat162float(__float2bfloat16(v11));
    float r12 = v12 - __bfloat162float(__float2bfloat16(v12));
    float r13 = v13 - __bfloat162float(__float2bfloat16(v13));
    lo4.x = pk(r00, r01); lo4.y = pk(r10, r11);
    lo4.z = pk(r02, r03); lo4.w = pk(r12, r13);
    size_t base = (size_t)id * 64 + l;
    xp[base] = hi4;
    xp[base + 32] = lo4;
}

// ---------------- persistent mma.sync RNN --------------------------------
// 128 CTAs x 256 threads (8 warps, wm 0-3 x wn 0-1). CTA tile M64 x N32;
// warp tile m16 x n16. Depth-8 A register ring; x chunks processed first,
// prefetched BEFORE the step barrier (x is h-independent).
__global__ void __launch_bounds__(256, 1) rnn_mma(
    float* __restrict__ out, const float* __restrict__ Wh,
    const float* __restrict__ Wx, const float* __restrict__ Wo,
    const uint4* __restrict__ xp, uint4* __restrict__ hA,
    float* __restrict__ hf)
{
    extern __shared__ __align__(16) uint8_t smem[];
    const int tid = threadIdx.x, l = tid & 31;
    const int wid = tid >> 5, wm = wid >> 1, wn = wid & 1;
    const int bid = blockIdx.x;
    const int grp = bid >> 5;              // m-group (4 groups of 32 CTAs)
    const int m0 = grp << 6;               // batch tile: 4 x 64
    const int n0 = (bid & 31) << 5;        // hidden tile: 32 x 32
    const uint32_t sB = smem_u32(smem);

    // ---- one-time: pack B slice (rows n0..n0+31 of [Wh | Wx]) into smem ----
    // layout: [kc][wn][hl(512B)] ; per lane 16B = {fr0:b0,b1 | fr1:b0,b1}
    for (int e = tid; e < 32 * 1088; e += 256) {
        int nl = e / 1088, k = e - nl * 1088;
        float v = (k < 1024) ? Wh[(size_t)(n0 + nl) * 1024 + k]
                             : Wx[(size_t)(n0 + nl) * 64 + (k - 1024)];
        __nv_bfloat16 h = __float2bfloat16(v);
        __nv_bfloat16 lo = __float2bfloat16(v - __bfloat162float(h));
        int kc = k >> 4, fr = nl >> 3;
        int wnd = fr >> 1, f01 = fr & 1;
        int lane = ((nl & 7) << 2) | ((k & 7) >> 1);
        int w = (k >> 3) & 1, hb = k & 1;
        uint32_t off = (uint32_t)kc * 2048 + (uint32_t)wnd * 1024 +
                       lane * 16 + f01 * 8 + w * 4 + hb * 2;
        *reinterpret_cast<__nv_bfloat16*>(smem + off)       = h;
        *reinterpret_cast<__nv_bfloat16*>(smem + off + 512) = lo;
    }
    // zero this group's slice of h buffer 0 (h_{-1} = 0)
    {
        uint4 z = make_uint4(0, 0, 0, 0);
        const int base = grp * 16384;      // 4 mt tiles x 64 kc x 2 x 32
        for (int i = (bid & 31) * 256 + tid; i < 16384; i += 32 * 256)
            hA[base + i] = z;
    }

    const int mtg = (m0 >> 4) + wm;        // this warp's global m16 tile
    const int kcd = (n0 >> 4) + wn;        // epilogue dest kc (next-step A chunk)

    uint4 sAh[8], sAl[8];
    // prefetch step-0 x chunks into slots 0-3 (x is h-independent)
#pragma unroll
    for (int p = 0; p < 4; ++p) {
        const uint4* ap = xp + ((size_t)(mtg * 4 + p) * 2) * 32 + l;
        sAh[p] = ap[0];
        sAl[p] = ap[32];
    }
    group_sync(grp);

    for (int t = 0; t < T_; ++t) {
        const uint4* __restrict__ hcur = hA + (size_t)(t & 1) * HBUF;
        uint4* __restrict__ hnxt       = hA + (size_t)((t + 1) & 1) * HBUF;

        // after barrier: prefetch h chunks 0-3 into slots 4-7
#pragma unroll
        for (int p = 0; p < 4; ++p) {
            const uint4* ap = hcur + ((size_t)(mtg * 64 + p) * 2) * 32 + l;
            sAh[4 + p] = ap[0];
            sAl[4 + p] = ap[32];
        }

        float chh[2][4], chl_[2][4], clh[2][4];
#pragma unroll
        for (int f = 0; f < 2; ++f)
#pragma unroll
            for (int j = 0; j < 4; ++j)
                chh[f][j] = chl_[f][j] = clh[f][j] = 0.f;

        const uint32_t bbase = sB + (uint32_t)wn * 1024 + l * 16;

        // ---- x chunks first (kc 64..67, slots 0..3); prefetch h 4..7 -------
#pragma unroll
        for (int i = 0; i < 4; ++i) {
            uint32_t bh[4], bl[4];
            const uint32_t ba = bbase + (uint32_t)(64 + i) * 2048;
            lds128(bh, ba);
            lds128(bl, ba + 512);
            const uint32_t* ah = reinterpret_cast<const uint32_t*>(&sAh[i]);
            const uint32_t* al = reinterpret_cast<const uint32_t*>(&sAl[i]);
            mma16816(chh[0],  ah, bh);      mma16816(chh[1],  ah, bh + 2);
            mma16816(chl_[0], ah, bl);      mma16816(chl_[1], ah, bl + 2);
            mma16816(clh[0],  al, bh);      mma16816(clh[1],  al, bh + 2);
            const uint4* ap = hcur + ((size_t)(mtg * 64 + (i + 4)) * 2) * 32 + l;
            sAh[i] = ap[0];
            sAl[i] = ap[32];
        }
        // ---- h chunks (kc 0..63), rolling depth-8 prefetch ------------------
#pragma unroll 4
        for (int i = 4; i < 68; ++i) {
            const int s = i & 7;
            uint32_t bh[4], bl[4];
            const uint32_t ba = bbase + (uint32_t)(i - 4) * 2048;
            lds128(bh, ba);
            lds128(bl, ba + 512);
            const uint32_t* ah = reinterpret_cast<const uint32_t*>(&sAh[s]);
            const uint32_t* al = reinterpret_cast<const uint32_t*>(&sAl[s]);
            mma16816(chh[0],  ah, bh);      mma16816(chh[1],  ah, bh + 2);
            mma16816(chl_[0], ah, bl);      mma16816(chl_[1], ah, bl + 2);
            mma16816(clh[0],  al, bh);      mma16816(clh[1],  al, bh + 2);
            if (i + 8 < 68) {
                const uint4* ap = hcur + ((size_t)(mtg * 64 + (i + 4)) * 2) * 32 + l;
                sAh[s] = ap[0];
                sAl[s] = ap[32];
            }
        }

        // ---- epilogue: relu, bf16 split, store in next-step A-frag layout ----
        {
            float v[2][4], r[2][4];
#pragma unroll
            for (int f = 0; f < 2; ++f)
#pragma unroll
                for (int j = 0; j < 4; ++j) {
                    float s = chh[f][j] + chl_[f][j] + clh[f][j];
                    s = fmaxf(s, 0.f);
                    v[f][j] = s;
                    r[f][j] = s - __bfloat162float(__float2bfloat16(s));
                }
            uint4 hi4, lo4;
            hi4.x = pk(v[0][0], v[0][1]);  hi4.y = pk(v[0][2], v[0][3]);
            hi4.z = pk(v[1][0], v[1][1]);  hi4.w = pk(v[1][2], v[1][3]);
            lo4.x = pk(r[0][0], r[0][1]);  lo4.y = pk(r[0][2], r[0][3]);
            lo4.z = pk(r[1][0], r[1][1]);  lo4.w = pk(r[1][2], r[1][3]);
            uint4* dst = hnxt + ((size_t)(mtg * 64 + kcd) * 2) * 32 + l;
            dst[0]  = hi4;
            dst[32] = lo4;
            if (t == T_ - 1) {
                int r0 = mtg * 16 + (l >> 2);
                int c0 = n0 + wn * 16 + 2 * (l & 3);
                *(float2*)&hf[(size_t)r0 * H_ + c0]           = make_float2(v[0][0], v[0][1]);
                *(float2*)&hf[(size_t)(r0 + 8) * H_ + c0]     = make_float2(v[0][2], v[0][3]);
                *(float2*)&hf[(size_t)r0 * H_ + c0 + 8]       = make_float2(v[1][0], v[1][1]);
                *(float2*)&hf[(size_t)(r0 + 8) * H_ + c0 + 8] = make_float2(v[1][2], v[1][3]);
            }
        }

        // pre-barrier: prefetch next step's x chunks into slots 0-3
        {
            const int tn = (t + 1 < T_) ? (t + 1) : t;
            const uint4* __restrict__ xpn = xp + (size_t)tn * 4096;
#pragma unroll
            for (int p = 0; p < 4; ++p) {
                const uint4* ap = xpn + ((size_t)(mtg * 4 + p) * 2) * 32 + l;
                sAh[p] = ap[0];
                sAl[p] = ap[32];
            }
        }
        group_sync(grp);
    }

    // ---- final: out[m][o] = sum_k h[m][k] * Wo[o][k]; 2 batch rows per CTA ---
    // (rows bid*2, bid*2+1 belong to this CTA's own m-group: synced above)
    {
        float* sw = (float*)smem;                 // [128][129] padded
        float* sh = (float*)smem + 128 * 129;     // [2][1024]
        const int m = bid * 2;
        const int half = tid >> 7, o = tid & 127;
        __syncthreads();
        for (int i = tid; i < 2 * H_; i += 256)
            sh[i] = hf[(size_t)(m + (i >> 10)) * H_ + (i & 1023)];
        float acc = 0.f;
        for (int k0 = 0; k0 < H_; k0 += 128) {
            __syncthreads();
            for (int i = tid; i < 128 * 128; i += 256) {
                int oo = i >> 7, kk = i & 127;
                sw[oo * 129 + kk] = Wo[(size_t)oo * H_ + k0 + kk];
            }
            __syncthreads();
#pragma unroll 8
            for (int kk = 0; kk < 128; ++kk)
                acc = fmaf(sh[half * H_ + k0 + kk], sw[o * 129 + kk], acc);
        }
        out[(size_t)(m + half) * OUT_ + o] = acc;
    }
}

// ---------------- launch --------------------------------------------------
extern "C" void kernel_launch(void* const* d_in, const int* in_sizes, int n_in,
                              void* d_out, int out_size) {
    (void)in_sizes; (void)n_in; (void)out_size;
    const float* x  = (const float*)d_in[0];
    const float* Wh = (const float*)d_in[1];
    const float* Wx = (const float*)d_in[2];
    const float* Wo = (const float*)d_in[3];
    float* out = (float*)d_out;

    uint4 *phA, *pxp;
    float* phf;
    cudaGetSymbolAddress((void**)&phA, g_hA);
    cudaGetSymbolAddress((void**)&pxp, g_xp);
    cudaGetSymbolAddress((void**)&phf, g_hf);

    pack_x<<<4096, 256>>>(x, pxp);

    cudaFuncSetAttribute(rnn_mma, cudaFuncAttributeMaxDynamicSharedMemorySize, SMEM_BYTES);
    rnn_mma<<<NCTA, 256, SMEM_BYTES>>>(out, Wh, Wx, Wo, pxp, phA, phf);
}

// round 7
// speedup vs baseline: 1.4536x; 1.4536x over previous
#include <cuda_runtime.h>
#include <cuda_bf16.h>
#include <cstdint>

#define B_    256
#define T_    512
#define IN_   64
#define H_    1024
#define OUT_  128
#define NCTA  128
#define NKC   68
#define HBUF  (16 * 64 * 2 * 32)      // uint4s per h buffer: [mt][kc][hi/lo][lane]
#define B_BYTES   139264              // 68 kc x 2048 B (frag-packed, hi|lo)
#define EXCH_OFF  B_BYTES
#define SMEM_BYTES (B_BYTES + 8192)   // + exchange region (4 wm x 2KB)

// ---------------- persistent device scratch ------------------------------
__device__ uint4 g_hA[2 * HBUF];                     // ping-pong h, A-frag packed
__device__ uint4 g_xp[(size_t)T_ * 16 * 4 * 2 * 32]; // x, A-frag packed per t
__device__ float g_hf[B_ * H_];                      // final h, plain fp32
__device__ unsigned g_bar_count;
__device__ volatile unsigned g_bar_gen;

// ---------------- helpers -------------------------------------------------
__device__ __forceinline__ uint32_t smem_u32(const void* p) {
    uint32_t a;
    asm("{ .reg .u64 t; cvta.to.shared.u64 t, %1; cvt.u32.u64 %0, t; }"
        : "=r"(a) : "l"(p));
    return a;
}

__device__ __forceinline__ uint32_t pk(float a, float b) {
    __nv_bfloat162 t = __floats2bfloat162_rn(a, b);
    return *reinterpret_cast<uint32_t*>(&t);
}

__device__ __forceinline__ void lds128(uint32_t* r, uint32_t a) {
    asm("ld.shared.v4.b32 {%0,%1,%2,%3}, [%4];"
        : "=r"(r[0]), "=r"(r[1]), "=r"(r[2]), "=r"(r[3]) : "r"(a));
}

__device__ __forceinline__ void mma16816(float* c, const uint32_t* a, const uint32_t* b) {
    asm("mma.sync.aligned.m16n8k16.row.col.f32.bf16.bf16.f32 "
        "{%0,%1,%2,%3}, {%4,%5,%6,%7}, {%8,%9}, {%0,%1,%2,%3};"
        : "+f"(c[0]), "+f"(c[1]), "+f"(c[2]), "+f"(c[3])
        : "r"(a[0]), "r"(a[1]), "r"(a[2]), "r"(a[3]), "r"(b[0]), "r"(b[1]));
}

__device__ __forceinline__ void grid_sync() {
    __syncthreads();
    if (threadIdx.x == 0) {
        __threadfence();
        unsigned gen = g_bar_gen;
        if (atomicAdd(&g_bar_count, 1u) == NCTA - 1u) {
            atomicExch(&g_bar_count, 0u);
            __threadfence();
            g_bar_gen = gen + 1u;
        } else {
            while (g_bar_gen == gen) { }
        }
        __threadfence();
    }
    __syncthreads();
}

// ---------------- pack x into A-fragment layout (one-time) ----------------
__global__ void pack_x(const float* __restrict__ x, uint4* __restrict__ xp) {
    int id = blockIdx.x * (blockDim.x >> 5) + (threadIdx.x >> 5);
    int l  = threadIdx.x & 31;
    if (id >= T_ * 16 * 4) return;
    int t = id >> 6, mt = (id >> 2) & 15, kcx = id & 3;
    int b0 = mt * 16 + (l >> 2), b1 = b0 + 8;
    int i0 = kcx * 16 + 2 * (l & 3);
    const float* x0 = x + ((size_t)b0 * T_ + t) * IN_;
    const float* x1 = x + ((size_t)b1 * T_ + t) * IN_;
    float v00 = x0[i0], v01 = x0[i0 + 1], v02 = x0[i0 + 8], v03 = x0[i0 + 9];
    float v10 = x1[i0], v11 = x1[i0 + 1], v12 = x1[i0 + 8], v13 = x1[i0 + 9];
    uint4 hi4, lo4;
    hi4.x = pk(v00, v01); hi4.y = pk(v10, v11);
    hi4.z = pk(v02, v03); hi4.w = pk(v12, v13);
    float r00 = v00 - __bfloat162float(__float2bfloat16(v00));
    float r01 = v01 - __bfloat162float(__float2bfloat16(v01));
    float r02 = v02 - __bfloat162float(__float2bfloat16(v02));
    float r03 = v03 - __bfloat162float(__float2bfloat16(v03));
    float r10 = v10 - __bfloat162float(__float2bfloat16(v10));
    float r11 = v11 - __bfloat162float(__float2bfloat16(v11));
    float r12 = v12 - __bfloat162float(__float2bfloat16(v12));
    float r13 = v13 - __bfloat162float(__float2bfloat16(v13));
    lo4.x = pk(r00, r01); lo4.y = pk(r10, r11);
    lo4.z = pk(r02, r03); lo4.w = pk(r12, r13);
    size_t base = (size_t)id * 64 + l;
    xp[base] = hi4;
    xp[base + 32] = lo4;
}

// ---------------- persistent mma.sync RNN --------------------------------
// 128 CTAs x 256 threads. CTA tile M64 x N32. 8 warps: role = wid>>2
// (role0: A_hi x (B_hi + B_lo), role1: A_lo x B_hi), wm = wid&3, each warp
// covers the FULL n32 tile. Each warp loads only ONE A part per chunk.
__global__ void __launch_bounds__(256, 1) rnn_mma(
    float* __restrict__ out, const float* __restrict__ Wh,
    const float* __restrict__ Wx, const float* __restrict__ Wo,
    const uint4* __restrict__ xp, uint4* __restrict__ hA,
    float* __restrict__ hf)
{
    extern __shared__ __align__(16) uint8_t smem[];
    const int tid = threadIdx.x, l = tid & 31;
    const int wid = tid >> 5;
    const int role = wid >> 2, wm = wid & 3;   // one role0 + one role1 per SMSP
    const int bid = blockIdx.x;
    const int m0 = (bid >> 5) << 6;            // batch tile: 4 x 64
    const int n0 = (bid & 31) << 5;            // hidden tile: 32 x 32
    const uint32_t sB = smem_u32(smem);

    // ---- one-time: pack B slice (rows n0..n0+31 of [Wh | Wx]) into smem ----
    // per kc (2048B): hi [frpair0 512 | frpair1 512] then lo [.. | ..]
    // per lane 16B = frag f(8B: b0,b1) | frag f+1(8B)
    for (int e = tid; e < 32 * 1088; e += 256) {
        int nl = e / 1088, k = e - nl * 1088;
        float v = (k < 1024) ? Wh[(size_t)(n0 + nl) * 1024 + k]
                             : Wx[(size_t)(n0 + nl) * 64 + (k - 1024)];
        __nv_bfloat16 h = __float2bfloat16(v);
        __nv_bfloat16 lo = __float2bfloat16(v - __bfloat162float(h));
        int kc = k >> 4, fr = nl >> 3, frp = fr >> 1, f01 = fr & 1;
        int lane = ((nl & 7) << 2) | ((k & 7) >> 1);
        int w = (k >> 3) & 1, hb = k & 1;
        uint32_t off = (uint32_t)kc * 2048 + frp * 512 + lane * 16 + f01 * 8 + w * 4 + hb * 2;
        *reinterpret_cast<__nv_bfloat16*>(smem + off)        = h;
        *reinterpret_cast<__nv_bfloat16*>(smem + off + 1024) = lo;
    }
    // zero h buffer 0 (h_{-1} = 0)
    {
        uint4 z = make_uint4(0, 0, 0, 0);
        for (int i = bid * 256 + tid; i < HBUF; i += NCTA * 256) hA[i] = z;
    }
    grid_sync();

    const int mtg  = (m0 >> 4) + wm;           // this warp's global m16 tile
    const int kcd0 = n0 >> 4;                  // first dest kc (warp covers n32)

    for (int t = 0; t < T_; ++t) {
        const uint4* __restrict__ hcur = hA + (size_t)(t & 1) * HBUF;
        uint4* __restrict__ hnxt       = hA + (size_t)((t + 1) & 1) * HBUF;
        const uint4* __restrict__ xpt  = xp + (size_t)t * 4096;

        float acc[4][4];
#pragma unroll
        for (int f = 0; f < 4; ++f)
#pragma unroll
            for (int j = 0; j < 4; ++j) acc[f][j] = 0.f;

        // A pointer for chunk kc: role selects hi (0) or lo (1) part
        auto aptr = [&](int kc) -> const uint4* {
            return (kc < 64)
                ? hcur + ((size_t)(mtg * 64 + kc) * 2 + role) * 32 + l
                : xpt  + ((size_t)(mtg * 4 + (kc - 64)) * 2 + role) * 32 + l;
        };

        uint4 sA[4];
#pragma unroll
        for (int p = 0; p < 4; ++p) sA[p] = *aptr(p);

#pragma unroll 4
        for (int kc = 0; kc < NKC; ++kc) {
            const int s = kc & 3;
            const uint32_t ba = sB + (uint32_t)kc * 2048 + l * 16;
            uint32_t bh[8];
            lds128(bh,     ba);        // hi frags 0,1
            lds128(bh + 4, ba + 512);  // hi frags 2,3
            const uint32_t* a = reinterpret_cast<const uint32_t*>(&sA[s]);
            mma16816(acc[0], a, bh);      mma16816(acc[1], a, bh + 2);
            mma16816(acc[2], a, bh + 4);  mma16816(acc[3], a, bh + 6);
            if (role == 0) {               // uniform per warp
                uint32_t bl[8];
                lds128(bl,     ba + 1024);
                lds128(bl + 4, ba + 1536);
                mma16816(acc[0], a, bl);      mma16816(acc[1], a, bl + 2);
                mma16816(acc[2], a, bl + 4);  mma16816(acc[3], a, bl + 6);
            }
            if (kc + 4 < NKC) sA[s] = *aptr(kc + 4);
        }

        // ---- combine terms: role1 -> smem, role0 adds, relu, split, store ----
        if (role == 1) {
            const uint32_t eb = sB + EXCH_OFF + (uint32_t)wm * 2048 + l * 16;
#pragma unroll
            for (int f = 0; f < 4; ++f)
                *reinterpret_cast<float4*>(smem + (eb - sB) + f * 512) =
                    make_float4(acc[f][0], acc[f][1], acc[f][2], acc[f][3]);
        }
        __syncthreads();
        if (role == 0) {
            const uint32_t eb = EXCH_OFF + (uint32_t)wm * 2048 + l * 16;
            float v[4][4], r[4][4];
#pragma unroll
            for (int f = 0; f < 4; ++f) {
                float4 p = *reinterpret_cast<const float4*>(smem + eb + f * 512);
                float s0 = fmaxf(acc[f][0] + p.x, 0.f);
                float s1 = fmaxf(acc[f][1] + p.y, 0.f);
                float s2 = fmaxf(acc[f][2] + p.z, 0.f);
                float s3 = fmaxf(acc[f][3] + p.w, 0.f);
                v[f][0] = s0; v[f][1] = s1; v[f][2] = s2; v[f][3] = s3;
                r[f][0] = s0 - __bfloat162float(__float2bfloat16(s0));
                r[f][1] = s1 - __bfloat162float(__float2bfloat16(s1));
                r[f][2] = s2 - __bfloat162float(__float2bfloat16(s2));
                r[f][3] = s3 - __bfloat162float(__float2bfloat16(s3));
            }
            // frags (0,1) -> chunk kcd0 ; frags (2,3) -> chunk kcd0+1
#pragma unroll
            for (int cpair = 0; cpair < 2; ++cpair) {
                const int f = cpair * 2;
                uint4 hi4, lo4;
                hi4.x = pk(v[f][0], v[f][1]);     hi4.y = pk(v[f][2], v[f][3]);
                hi4.z = pk(v[f + 1][0], v[f + 1][1]); hi4.w = pk(v[f + 1][2], v[f + 1][3]);
                lo4.x = pk(r[f][0], r[f][1]);     lo4.y = pk(r[f][2], r[f][3]);
                lo4.z = pk(r[f + 1][0], r[f + 1][1]); lo4.w = pk(r[f + 1][2], r[f + 1][3]);
                uint4* dst = hnxt + ((size_t)(mtg * 64 + kcd0 + cpair) * 2) * 32 + l;
                dst[0]  = hi4;
                dst[32] = lo4;
            }
            if (t == T_ - 1) {
                int r0 = mtg * 16 + (l >> 2);
#pragma unroll
                for (int f = 0; f < 4; ++f) {
                    int c0 = n0 + f * 8 + 2 * (l & 3);
                    *(float2*)&hf[(size_t)r0 * H_ + c0]       = make_float2(v[f][0], v[f][1]);
                    *(float2*)&hf[(size_t)(r0 + 8) * H_ + c0] = make_float2(v[f][2], v[f][3]);
                }
            }
        }
        grid_sync();
    }

    // ---- final: out[m][o] = sum_k h[m][k] * Wo[o][k]; 2 batch rows per CTA ---
    {
        float* sw = (float*)smem;                 // [128][129] padded
        float* sh = (float*)smem + 128 * 129;     // [2][1024]
        const int m = bid * 2;
        const int half = tid >> 7, o = tid & 127;
        __syncthreads();
        for (int i = tid; i < 2 * H_; i += 256)
            sh[i] = hf[(size_t)(m + (i >> 10)) * H_ + (i & 1023)];
        float acc = 0.f;
        for (int k0 = 0; k0 < H_; k0 += 128) {
            __syncthreads();
            for (int i = tid; i < 128 * 128; i += 256) {
                int oo = i >> 7, kk = i & 127;
                sw[oo * 129 + kk] = Wo[(size_t)oo * H_ + k0 + kk];
            }
            __syncthreads();
#pragma unroll 8
            for (int kk = 0; kk < 128; ++kk)
                acc = fmaf(sh[half * H_ + k0 + kk], sw[o * 129 + kk], acc);
        }
        out[(size_t)(m + half) * OUT_ + o] = acc;
    }
}

// ---------------- launch --------------------------------------------------
extern "C" void kernel_launch(void* const* d_in, const int* in_sizes, int n_in,
                              void* d_out, int out_size) {
    (void)in_sizes; (void)n_in; (void)out_size;
    const float* x  = (const float*)d_in[0];
    const float* Wh = (const float*)d_in[1];
    const float* Wx = (const float*)d_in[2];
    const float* Wo = (const float*)d_in[3];
    float* out = (float*)d_out;

    uint4 *phA, *pxp;
    float* phf;
    cudaGetSymbolAddress((void**)&phA, g_hA);
    cudaGetSymbolAddress((void**)&pxp, g_xp);
    cudaGetSymbolAddress((void**)&phf, g_hf);

    pack_x<<<4096, 256>>>(x, pxp);

    cudaFuncSetAttribute(rnn_mma, cudaFuncAttributeMaxDynamicSharedMemorySize, SMEM_BYTES);
    rnn_mma<<<NCTA, 256, SMEM_BYTES>>>(out, Wh, Wx, Wo, pxp, phA, phf);
}

// round 9
// speedup vs baseline: 1.9804x; 1.3624x over previous
#include <cuda_runtime.h>
#include <cuda_bf16.h>
#include <cstdint>

#define B_    256
#define T_    512
#define IN_   64
#define H_    1024
#define OUT_  128
#define NCTA  128
#define NKC   68                      // K chunks of 16: 64 (h) + 4 (x_t)
#define HBUF  (16 * 64 * 2 * 32)      // uint4s per h buffer: [mt][kc][hl][lane]
#define SMEM_BYTES (NKC * 4 * 2 * 256)   // 139264 B: B slice, frag-packed

// ---------------- persistent device scratch ------------------------------
__device__ uint4 g_hA[2 * HBUF];                   // ping-pong h, A-frag packed (2 MB)
__device__ uint4 g_xp[(size_t)T_ * 16 * 4 * 2 * 32]; // x, A-frag packed per t (32 MB)
__device__ float g_hf[B_ * H_];                    // final h, plain fp32
__device__ unsigned g_bar_count;
__device__ volatile unsigned g_bar_gen;

// ---------------- helpers -------------------------------------------------
__device__ __forceinline__ uint32_t smem_u32(const void* p) {
    uint32_t a;
    asm("{ .reg .u64 t; cvta.to.shared.u64 t, %1; cvt.u32.u64 %0, t; }"
        : "=r"(a) : "l"(p));
    return a;
}

__device__ __forceinline__ uint32_t pk(float a, float b) {
    __nv_bfloat162 t = __floats2bfloat162_rn(a, b);
    return *reinterpret_cast<uint32_t*>(&t);
}

__device__ __forceinline__ void lds64(uint32_t* r, uint32_t a) {
    asm("ld.shared.v2.b32 {%0,%1}, [%2];" : "=r"(r[0]), "=r"(r[1]) : "r"(a));
}

__device__ __forceinline__ void mma16816(float* c, const uint32_t* a, const uint32_t* b) {
    asm("mma.sync.aligned.m16n8k16.row.col.f32.bf16.bf16.f32 "
        "{%0,%1,%2,%3}, {%4,%5,%6,%7}, {%8,%9}, {%0,%1,%2,%3};"
        : "+f"(c[0]), "+f"(c[1]), "+f"(c[2]), "+f"(c[3])
        : "r"(a[0]), "r"(a[1]), "r"(a[2]), "r"(a[3]), "r"(b[0]), "r"(b[1]));
}

__device__ __forceinline__ void grid_sync() {
    __syncthreads();
    if (threadIdx.x == 0) {
        __threadfence();
        unsigned gen = g_bar_gen;
        if (atomicAdd(&g_bar_count, 1u) == NCTA - 1u) {
            atomicExch(&g_bar_count, 0u);
            __threadfence();
            g_bar_gen = gen + 1u;
        } else {
            while (g_bar_gen == gen) { }
        }
        __threadfence();
    }
    __syncthreads();
}

// ---------------- pack x into A-fragment layout (one-time) ----------------
__global__ void pack_x(const float* __restrict__ x, uint4* __restrict__ xp) {
    int id = blockIdx.x * (blockDim.x >> 5) + (threadIdx.x >> 5);
    int l  = threadIdx.x & 31;
    if (id >= T_ * 16 * 4) return;
    int t = id >> 6, mt = (id >> 2) & 15, kcx = id & 3;
    int b0 = mt * 16 + (l >> 2), b1 = b0 + 8;
    int i0 = kcx * 16 + 2 * (l & 3);
    const float* x0 = x + ((size_t)b0 * T_ + t) * IN_;
    const float* x1 = x + ((size_t)b1 * T_ + t) * IN_;
    float v00 = x0[i0], v01 = x0[i0 + 1], v02 = x0[i0 + 8], v03 = x0[i0 + 9];
    float v10 = x1[i0], v11 = x1[i0 + 1], v12 = x1[i0 + 8], v13 = x1[i0 + 9];
    uint4 hi4, lo4;
    hi4.x = pk(v00, v01); hi4.y = pk(v10, v11);
    hi4.z = pk(v02, v03); hi4.w = pk(v12, v13);
    float r00 = v00 - __bfloat162float(__float2bfloat16(v00));
    float r01 = v01 - __bfloat162float(__float2bfloat16(v01));
    float r02 = v02 - __bfloat162float(__float2bfloat16(v02));
    float r03 = v03 - __bfloat162float(__float2bfloat16(v03));
    float r10 = v10 - __bfloat162float(__float2bfloat16(v10));
    float r11 = v11 - __bfloat162float(__float2bfloat16(v11));
    float r12 = v12 - __bfloat162float(__float2bfloat16(v12));
    float r13 = v13 - __bfloat162float(__float2bfloat16(v13));
    lo4.x = pk(r00, r01); lo4.y = pk(r10, r11);
    lo4.z = pk(r02, r03); lo4.w = pk(r12, r13);
    size_t base = (size_t)id * 64 + l;
    xp[base] = hi4;
    xp[base + 32] = lo4;
}

// ---------------- persistent mma.sync RNN --------------------------------
// 128 CTAs x 256 threads (8 warps, wm 0-3 x wn 0-1). CTA tile M64 x N32;
// warp tile m16 x n16. A register ring depth 8 with STATIC slot indices:
// h chunks 0..63 under unroll-8 (64 % 8 == 0), x chunks peeled (slots 0-3).
__global__ void __launch_bounds__(256, 1) rnn_mma(
    float* __restrict__ out, const float* __restrict__ Wh,
    const float* __restrict__ Wx, const float* __restrict__ Wo,
    const uint4* __restrict__ xp, uint4* __restrict__ hA,
    float* __restrict__ hf)
{
    extern __shared__ __align__(16) uint8_t smem[];
    const int tid = threadIdx.x, l = tid & 31;
    const int wid = tid >> 5, wm = wid >> 1, wn = wid & 1;
    const int bid = blockIdx.x;
    const int m0 = (bid >> 5) << 6;        // batch tile: 4 x 64
    const int n0 = (bid & 31) << 5;        // hidden tile: 32 x 32
    const uint32_t sB = smem_u32(smem);

    // ---- one-time: pack B slice (rows n0..n0+31 of [Wh | Wx]) into smem ----
    for (int e = tid; e < 32 * 1088; e += 256) {
        int nl = e / 1088, k = e - nl * 1088;
        float v = (k < 1024) ? Wh[(size_t)(n0 + nl) * 1024 + k]
                             : Wx[(size_t)(n0 + nl) * 64 + (k - 1024)];
        __nv_bfloat16 h = __float2bfloat16(v);
        __nv_bfloat16 lo = __float2bfloat16(v - __bfloat162float(h));
        int kc = k >> 4, fr = nl >> 3;
        int lane = ((nl & 7) << 2) | ((k & 7) >> 1);
        int w = (k >> 3) & 1, hb = k & 1;
        uint32_t off = (uint32_t)((kc * 4 + fr) * 2) * 256 + lane * 8 + w * 4 + hb * 2;
        *reinterpret_cast<__nv_bfloat16*>(smem + off) = h;
        *reinterpret_cast<__nv_bfloat16*>(smem + off + 256) = lo;
    }
    // zero h buffer 0 (h_{-1} = 0)
    {
        uint4 z = make_uint4(0, 0, 0, 0);
        for (int i = bid * 256 + tid; i < HBUF; i += NCTA * 256) hA[i] = z;
    }
    grid_sync();

    const int mtg = (m0 >> 4) + wm;        // this warp's global m16 tile (0-15)
    const int kcd = (n0 >> 4) + wn;        // epilogue dest kc (next-step A chunk)

    for (int t = 0; t < T_; ++t) {
        const uint4* __restrict__ hcur = hA + (size_t)(t & 1) * HBUF;
        uint4* __restrict__ hnxt       = hA + (size_t)((t + 1) & 1) * HBUF;
        const uint4* __restrict__ xpt  = xp + (size_t)t * 4096;

        float chh[2][4], chl[2][4], clh[2][4];
#pragma unroll
        for (int f = 0; f < 2; ++f)
#pragma unroll
            for (int j = 0; j < 4; ++j)
                chh[f][j] = chl[f][j] = clh[f][j] = 0.f;

        auto ablk = [&](int kc) -> const uint4* {
            return (kc < 64)
                ? hcur + ((size_t)(mtg * 64 + kc) * 2) * 32 + l
                : xpt  + ((size_t)(mtg * 4 + (kc - 64)) * 2) * 32 + l;
        };

        uint4 sAh[8], sAl[8];
#pragma unroll
        for (int p = 0; p < 8; ++p) {
            const uint4* ap = ablk(p);
            sAh[p] = ap[0];
            sAl[p] = ap[32];
        }

        // ---- h chunks 0..63: unroll 8, slot kc&7 is static per body --------
#pragma unroll 8
        for (int kc = 0; kc < 64; ++kc) {
            const int s = kc & 7;
            uint32_t bh0[2], bh1[2], bl0[2], bl1[2];
            uint32_t ba = sB + (uint32_t)kc * 2048 + (uint32_t)(wn * 2) * 512 + l * 8;
            lds64(bh0, ba);        lds64(bl0, ba + 256);
            lds64(bh1, ba + 512);  lds64(bl1, ba + 768);

            const uint32_t* ah = reinterpret_cast<const uint32_t*>(&sAh[s]);
            const uint32_t* al = reinterpret_cast<const uint32_t*>(&sAl[s]);

            mma16816(chh[0], ah, bh0);  mma16816(chh[1], ah, bh1);
            mma16816(chl[0], ah, bl0);  mma16816(chl[1], ah, bl1);
            mma16816(clh[0], al, bh0);  mma16816(clh[1], al, bh1);

            if (kc < 60) {                       // prefetch chunk kc+8 (h or x)
                const uint4* ap = ablk(kc + 8);
                sAh[s] = ap[0];
                sAl[s] = ap[32];
            }
        }
        // ---- x chunks 64..67: slots 0..3 (static) ---------------------------
#pragma unroll
        for (int kc = 64; kc < 68; ++kc) {
            const int s = kc & 7;                // 0..3
            uint32_t bh0[2], bh1[2], bl0[2], bl1[2];
            uint32_t ba = sB + (uint32_t)kc * 2048 + (uint32_t)(wn * 2) * 512 + l * 8;
            lds64(bh0, ba);        lds64(bl0, ba + 256);
            lds64(bh1, ba + 512);  lds64(bl1, ba + 768);

            const uint32_t* ah = reinterpret_cast<const uint32_t*>(&sAh[s]);
            const uint32_t* al = reinterpret_cast<const uint32_t*>(&sAl[s]);

            mma16816(chh[0], ah, bh0);  mma16816(chh[1], ah, bh1);
            mma16816(chl[0], ah, bl0);  mma16816(chl[1], ah, bl1);
            mma16816(clh[0], al, bh0);  mma16816(clh[1], al, bh1);
        }

        // ---- epilogue: relu, bf16 split, store in next-step A-frag layout ----
        {
            float v[2][4], r[2][4];
#pragma unroll
            for (int f = 0; f < 2; ++f)
#pragma unroll
                for (int j = 0; j < 4; ++j) {
                    float s = chh[f][j] + chl[f][j] + clh[f][j];
                    s = fmaxf(s, 0.f);
                    v[f][j] = s;
                    r[f][j] = s - __bfloat162float(__float2bfloat16(s));
                }
            uint4 hi4, lo4;
            hi4.x = pk(v[0][0], v[0][1]);  hi4.y = pk(v[0][2], v[0][3]);
            hi4.z = pk(v[1][0], v[1][1]);  hi4.w = pk(v[1][2], v[1][3]);
            lo4.x = pk(r[0][0], r[0][1]);  lo4.y = pk(r[0][2], r[0][3]);
            lo4.z = pk(r[1][0], r[1][1]);  lo4.w = pk(r[1][2], r[1][3]);
            uint4* dst = hnxt + ((size_t)(mtg * 64 + kcd) * 2) * 32 + l;
            dst[0]  = hi4;
            dst[32] = lo4;
            if (t == T_ - 1) {
                int r0 = mtg * 16 + (l >> 2);
                int c0 = n0 + wn * 16 + 2 * (l & 3);
                *(float2*)&hf[(size_t)r0 * H_ + c0]           = make_float2(v[0][0], v[0][1]);
                *(float2*)&hf[(size_t)(r0 + 8) * H_ + c0]     = make_float2(v[0][2], v[0][3]);
                *(float2*)&hf[(size_t)r0 * H_ + c0 + 8]       = make_float2(v[1][0], v[1][1]);
                *(float2*)&hf[(size_t)(r0 + 8) * H_ + c0 + 8] = make_float2(v[1][2], v[1][3]);
            }
        }
        grid_sync();
    }

    // ---- final: out[m][o] = sum_k h[m][k] * Wo[o][k]; 2 batch rows per CTA ---
    {
        float* sw = (float*)smem;                 // [128][129] padded
        float* sh = (float*)smem + 128 * 129;     // [2][1024]
        const int m = bid * 2;
        const int half = tid >> 7, o = tid & 127;
        for (int i = tid; i < 2 * H_; i += 256)
            sh[i] = hf[(size_t)(m + (i >> 10)) * H_ + (i & 1023)];
        float acc = 0.f;
        for (int k0 = 0; k0 < H_; k0 += 128) {
            __syncthreads();
            for (int i = tid; i < 128 * 128; i += 256) {
                int oo = i >> 7, kk = i & 127;
                sw[oo * 129 + kk] = Wo[(size_t)oo * H_ + k0 + kk];
            }
            __syncthreads();
#pragma unroll 8
            for (int kk = 0; kk < 128; ++kk)
                acc = fmaf(sh[half * H_ + k0 + kk], sw[o * 129 + kk], acc);
        }
        out[(size_t)(m + half) * OUT_ + o] = acc;
    }
}

// ---------------- launch --------------------------------------------------
extern "C" void kernel_launch(void* const* d_in, const int* in_sizes, int n_in,
                              void* d_out, int out_size) {
    (void)in_sizes; (void)n_in; (void)out_size;
    const float* x  = (const float*)d_in[0];
    const float* Wh = (const float*)d_in[1];
    const float* Wx = (const float*)d_in[2];
    const float* Wo = (const float*)d_in[3];
    float* out = (float*)d_out;

    uint4 *phA, *pxp;
    float* phf;
    cudaGetSymbolAddress((void**)&phA, g_hA);
    cudaGetSymbolAddress((void**)&pxp, g_xp);
    cudaGetSymbolAddress((void**)&phf, g_hf);

    pack_x<<<4096, 256>>>(x, pxp);

    cudaFuncSetAttribute(rnn_mma, cudaFuncAttributeMaxDynamicSharedMemorySize, SMEM_BYTES);
    rnn_mma<<<NCTA, 256, SMEM_BYTES>>>(out, Wh, Wx, Wo, pxp, phA, phf);
}

// round 10
// speedup vs baseline: 2.2010x; 1.1114x over previous
#include <cuda_runtime.h>
#include <cuda_bf16.h>
#include <cstdint>

#define B_    256
#define T_    512
#define IN_   64
#define H_    1024
#define OUT_  128
#define NCTA  128
#define HBUF  (16 * 64 * 2 * 32)      // uint4s per h buffer: [mt][kc][hl][lane]
#define B_BYTES   139264              // 68 kc x 2048 B (frag-pair interleaved, hi|lo)
#define EXCH_OFF  B_BYTES             // 4 wm x 2048 B exchange
#define SMEM_BYTES (B_BYTES + 8192)

// ---------------- persistent device scratch ------------------------------
__device__ uint4 g_hA[2 * HBUF];                     // ping-pong h, A-frag packed
__device__ uint4 g_xp[(size_t)T_ * 16 * 4 * 2 * 32]; // x, A-frag packed per t
__device__ float g_hf[B_ * H_];                      // final h, plain fp32
__device__ unsigned g_bar_count;
__device__ volatile unsigned g_bar_gen;

// ---------------- helpers -------------------------------------------------
__device__ __forceinline__ uint32_t smem_u32(const void* p) {
    uint32_t a;
    asm("{ .reg .u64 t; cvta.to.shared.u64 t, %1; cvt.u32.u64 %0, t; }"
        : "=r"(a) : "l"(p));
    return a;
}

__device__ __forceinline__ uint32_t pk(float a, float b) {
    __nv_bfloat162 t = __floats2bfloat162_rn(a, b);
    return *reinterpret_cast<uint32_t*>(&t);
}

__device__ __forceinline__ void lds128(uint32_t* r, uint32_t a) {
    asm("ld.shared.v4.b32 {%0,%1,%2,%3}, [%4];"
        : "=r"(r[0]), "=r"(r[1]), "=r"(r[2]), "=r"(r[3]) : "r"(a));
}

__device__ __forceinline__ void mma16816(float* c, const uint32_t* a, const uint32_t* b) {
    asm("mma.sync.aligned.m16n8k16.row.col.f32.bf16.bf16.f32 "
        "{%0,%1,%2,%3}, {%4,%5,%6,%7}, {%8,%9}, {%0,%1,%2,%3};"
        : "+f"(c[0]), "+f"(c[1]), "+f"(c[2]), "+f"(c[3])
        : "r"(a[0]), "r"(a[1]), "r"(a[2]), "r"(a[3]), "r"(b[0]), "r"(b[1]));
}

__device__ __forceinline__ void grid_sync() {
    __syncthreads();
    if (threadIdx.x == 0) {
        __threadfence();
        unsigned gen = g_bar_gen;
        if (atomicAdd(&g_bar_count, 1u) == NCTA - 1u) {
            atomicExch(&g_bar_count, 0u);
            __threadfence();
            g_bar_gen = gen + 1u;
        } else {
            while (g_bar_gen == gen) { }
        }
        __threadfence();
    }
    __syncthreads();
}

// ---------------- pack x into A-fragment layout (one-time) ----------------
__global__ void pack_x(const float* __restrict__ x, uint4* __restrict__ xp) {
    int id = blockIdx.x * (blockDim.x >> 5) + (threadIdx.x >> 5);
    int l  = threadIdx.x & 31;
    if (id >= T_ * 16 * 4) return;
    int t = id >> 6, mt = (id >> 2) & 15, kcx = id & 3;
    int b0 = mt * 16 + (l >> 2), b1 = b0 + 8;
    int i0 = kcx * 16 + 2 * (l & 3);
    const float* x0 = x + ((size_t)b0 * T_ + t) * IN_;
    const float* x1 = x + ((size_t)b1 * T_ + t) * IN_;
    float v00 = x0[i0], v01 = x0[i0 + 1], v02 = x0[i0 + 8], v03 = x0[i0 + 9];
    float v10 = x1[i0], v11 = x1[i0 + 1], v12 = x1[i0 + 8], v13 = x1[i0 + 9];
    uint4 hi4, lo4;
    hi4.x = pk(v00, v01); hi4.y = pk(v10, v11);
    hi4.z = pk(v02, v03); hi4.w = pk(v12, v13);
    float r00 = v00 - __bfloat162float(__float2bfloat16(v00));
    float r01 = v01 - __bfloat162float(__float2bfloat16(v01));
    float r02 = v02 - __bfloat162float(__float2bfloat16(v02));
    float r03 = v03 - __bfloat162float(__float2bfloat16(v03));
    float r10 = v10 - __bfloat162float(__float2bfloat16(v10));
    float r11 = v11 - __bfloat162float(__float2bfloat16(v11));
    float r12 = v12 - __bfloat162float(__float2bfloat16(v12));
    float r13 = v13 - __bfloat162float(__float2bfloat16(v13));
    lo4.x = pk(r00, r01); lo4.y = pk(r10, r11);
    lo4.z = pk(r02, r03); lo4.w = pk(r12, r13);
    size_t base = (size_t)id * 64 + l;
    xp[base] = hi4;
    xp[base + 32] = lo4;
}

// ---------------- persistent mma.sync RNN --------------------------------
// 128 CTAs x 256 threads. CTA tile M64 x N32. Warps: wm = wid&3 (m16 tile),
// wk = wid>>2 (K half: chunks [wk*34, wk*34+34)). Each warp covers full n32
// => every A fragment loaded by exactly ONE warp (A traffic halved vs R9).
// wk partial sums combined once per step via an 8KB smem exchange.
__global__ void __launch_bounds__(256, 1) rnn_mma(
    float* __restrict__ out, const float* __restrict__ Wh,
    const float* __restrict__ Wx, const float* __restrict__ Wo,
    const uint4* __restrict__ xp, uint4* __restrict__ hA,
    float* __restrict__ hf)
{
    extern __shared__ __align__(16) uint8_t smem[];
    const int tid = threadIdx.x, l = tid & 31;
    const int wid = tid >> 5;
    const int wm = wid & 3, wk = wid >> 2;     // one wk0 + one wk1 per SMSP
    const int bid = blockIdx.x;
    const int m0 = (bid >> 5) << 6;            // batch tile: 4 x 64
    const int n0 = (bid & 31) << 5;            // hidden tile: 32 x 32
    const uint32_t sB = smem_u32(smem);

    // ---- one-time: pack B slice (rows n0..n0+31 of [Wh | Wx]) into smem ----
    // per kc (2048B): hi [frpair0 512 | frpair1 512] then lo at +1024.
    // per lane 16B = frag f(8B: b0,b1) | frag f+1(8B)  -> LDS.128 loads 2 frags
    for (int e = tid; e < 32 * 1088; e += 256) {
        int nl = e / 1088, k = e - nl * 1088;
        float v = (k < 1024) ? Wh[(size_t)(n0 + nl) * 1024 + k]
                             : Wx[(size_t)(n0 + nl) * 64 + (k - 1024)];
        __nv_bfloat16 h = __float2bfloat16(v);
        __nv_bfloat16 lo = __float2bfloat16(v - __bfloat162float(h));
        int kc = k >> 4, fr = nl >> 3, frp = fr >> 1, f01 = fr & 1;
        int lane = ((nl & 7) << 2) | ((k & 7) >> 1);
        int w = (k >> 3) & 1, hb = k & 1;
        uint32_t off = (uint32_t)kc * 2048 + frp * 512 + lane * 16 + f01 * 8 + w * 4 + hb * 2;
        *reinterpret_cast<__nv_bfloat16*>(smem + off)        = h;
        *reinterpret_cast<__nv_bfloat16*>(smem + off + 1024) = lo;
    }
    // zero h buffer 0 (h_{-1} = 0)
    {
        uint4 z = make_uint4(0, 0, 0, 0);
        for (int i = bid * 256 + tid; i < HBUF; i += NCTA * 256) hA[i] = z;
    }
    grid_sync();

    const int mtg   = (m0 >> 4) + wm;          // this warp's global m16 tile
    const int kcd0  = (n0 >> 4);               // epilogue dest kc (covers n32: 2 chunks)
    const int kbase = wk * 34;                 // this warp's first K chunk

    for (int t = 0; t < T_; ++t) {
        const uint4* __restrict__ hcur = hA + (size_t)(t & 1) * HBUF;
        uint4* __restrict__ hnxt       = hA + (size_t)((t + 1) & 1) * HBUF;
        const uint4* __restrict__ xpt  = xp + (size_t)t * 4096;

        float chh[4][4], chl_[4][4], clh[4][4];
#pragma unroll
        for (int f = 0; f < 4; ++f)
#pragma unroll
            for (int j = 0; j < 4; ++j)
                chh[f][j] = chl_[f][j] = clh[f][j] = 0.f;

        auto ablk = [&](int kc) -> const uint4* {
            return (kc < 64)
                ? hcur + ((size_t)(mtg * 64 + kc) * 2) * 32 + l
                : xpt  + ((size_t)(mtg * 4 + (kc - 64)) * 2) * 32 + l;
        };

        uint4 sAh[8], sAl[8];
#pragma unroll
        for (int p = 0; p < 8; ++p) {
            const uint4* ap = ablk(kbase + p);
            sAh[p] = ap[0];
            sAl[p] = ap[32];
        }

        // macro-less chunk body (12 MMAs, 4 B frags via 4x LDS.128)
        auto chunk = [&](int kc, const uint4& Ah, const uint4& Al) {
            const uint32_t ba = sB + (uint32_t)kc * 2048 + l * 16;
            uint32_t bh[8], bl[8];
            lds128(bh,     ba);         lds128(bh + 4, ba + 512);
            lds128(bl,     ba + 1024);  lds128(bl + 4, ba + 1536);
            const uint32_t* ah = reinterpret_cast<const uint32_t*>(&Ah);
            const uint32_t* al = reinterpret_cast<const uint32_t*>(&Al);
            mma16816(chh[0],  ah, bh);      mma16816(chh[1],  ah, bh + 2);
            mma16816(chh[2],  ah, bh + 4);  mma16816(chh[3],  ah, bh + 6);
            mma16816(chl_[0], ah, bl);      mma16816(chl_[1], ah, bl + 2);
            mma16816(chl_[2], ah, bl + 4);  mma16816(chl_[3], ah, bl + 6);
            mma16816(clh[0],  al, bh);      mma16816(clh[1],  al, bh + 2);
            mma16816(clh[2],  al, bh + 4);  mma16816(clh[3],  al, bh + 6);
        };

        // ---- 32 chunks under unroll-8 (slot i&7 static), then 2 peeled ------
#pragma unroll 8
        for (int i = 0; i < 32; ++i) {
            const int s = i & 7;
            chunk(kbase + i, sAh[s], sAl[s]);
            if (i < 26) {                      // prefetch chunk i+8 (<= 33)
                const uint4* ap = ablk(kbase + i + 8);
                sAh[s] = ap[0];
                sAl[s] = ap[32];
            }
        }
        chunk(kbase + 32, sAh[0], sAl[0]);     // slots 0,1 hold chunks 32,33
        chunk(kbase + 33, sAh[1], sAl[1]);

        // ---- combine wk halves: wk1 -> smem, wk0 adds, relu, split, store ---
        if (wk == 1) {
#pragma unroll
            for (int f = 0; f < 4; ++f) {
                float4 s4 = make_float4(
                    chh[f][0] + chl_[f][0] + clh[f][0],
                    chh[f][1] + chl_[f][1] + clh[f][1],
                    chh[f][2] + chl_[f][2] + clh[f][2],
                    chh[f][3] + chl_[f][3] + clh[f][3]);
                *reinterpret_cast<float4*>(smem + EXCH_OFF + wm * 2048 + f * 512 + l * 16) = s4;
            }
        }
        __syncthreads();
        if (wk == 0) {
            float v[4][4], r[4][4];
#pragma unroll
            for (int f = 0; f < 4; ++f) {
                float4 p = *reinterpret_cast<const float4*>(
                    smem + EXCH_OFF + wm * 2048 + f * 512 + l * 16);
                float s0 = fmaxf(chh[f][0] + chl_[f][0] + clh[f][0] + p.x, 0.f);
                float s1 = fmaxf(chh[f][1] + chl_[f][1] + clh[f][1] + p.y, 0.f);
                float s2 = fmaxf(chh[f][2] + chl_[f][2] + clh[f][2] + p.z, 0.f);
                float s3 = fmaxf(chh[f][3] + chl_[f][3] + clh[f][3] + p.w, 0.f);
                v[f][0] = s0; v[f][1] = s1; v[f][2] = s2; v[f][3] = s3;
                r[f][0] = s0 - __bfloat162float(__float2bfloat16(s0));
                r[f][1] = s1 - __bfloat162float(__float2bfloat16(s1));
                r[f][2] = s2 - __bfloat162float(__float2bfloat16(s2));
                r[f][3] = s3 - __bfloat162float(__float2bfloat16(s3));
            }
            // frags (0,1) -> dest chunk kcd0 ; frags (2,3) -> kcd0+1
#pragma unroll
            for (int cpair = 0; cpair < 2; ++cpair) {
                const int f = cpair * 2;
                uint4 hi4, lo4;
                hi4.x = pk(v[f][0], v[f][1]);         hi4.y = pk(v[f][2], v[f][3]);
                hi4.z = pk(v[f + 1][0], v[f + 1][1]); hi4.w = pk(v[f + 1][2], v[f + 1][3]);
                lo4.x = pk(r[f][0], r[f][1]);         lo4.y = pk(r[f][2], r[f][3]);
                lo4.z = pk(r[f + 1][0], r[f + 1][1]); lo4.w = pk(r[f + 1][2], r[f + 1][3]);
                uint4* dst = hnxt + ((size_t)(mtg * 64 + kcd0 + cpair) * 2) * 32 + l;
                dst[0]  = hi4;
                dst[32] = lo4;
            }
            if (t == T_ - 1) {
                int r0 = mtg * 16 + (l >> 2);
#pragma unroll
                for (int f = 0; f < 4; ++f) {
                    int c0 = n0 + f * 8 + 2 * (l & 3);
                    *(float2*)&hf[(size_t)r0 * H_ + c0]       = make_float2(v[f][0], v[f][1]);
                    *(float2*)&hf[(size_t)(r0 + 8) * H_ + c0] = make_float2(v[f][2], v[f][3]);
                }
            }
        }
        grid_sync();
    }

    // ---- final: out[m][o] = sum_k h[m][k] * Wo[o][k]; 2 batch rows per CTA ---
    {
        float* sw = (float*)smem;                 // [128][129] padded
        float* sh = (float*)smem + 128 * 129;     // [2][1024]
        const int m = bid * 2;
        const int half = tid >> 7, o = tid & 127;
        for (int i = tid; i < 2 * H_; i += 256)
            sh[i] = hf[(size_t)(m + (i >> 10)) * H_ + (i & 1023)];
        float acc = 0.f;
        for (int k0 = 0; k0 < H_; k0 += 128) {
            __syncthreads();
            for (int i = tid; i < 128 * 128; i += 256) {
                int oo = i >> 7, kk = i & 127;
                sw[oo * 129 + kk] = Wo[(size_t)oo * H_ + k0 + kk];
            }
            __syncthreads();
#pragma unroll 8
            for (int kk = 0; kk < 128; ++kk)
                acc = fmaf(sh[half * H_ + k0 + kk], sw[o * 129 + kk], acc);
        }
        out[(size_t)(m + half) * OUT_ + o] = acc;
    }
}

// ---------------- launch --------------------------------------------------
extern "C" void kernel_launch(void* const* d_in, const int* in_sizes, int n_in,
                              void* d_out, int out_size) {
    (void)in_sizes; (void)n_in; (void)out_size;
    const float* x  = (const float*)d_in[0];
    const float* Wh = (const float*)d_in[1];
    const float* Wx = (const float*)d_in[2];
    const float* Wo = (const float*)d_in[3];
    float* out = (float*)d_out;

    uint4 *phA, *pxp;
    float* phf;
    cudaGetSymbolAddress((void**)&phA, g_hA);
    cudaGetSymbolAddress((void**)&pxp, g_xp);
    cudaGetSymbolAddress((void**)&phf, g_hf);

    pack_x<<<4096, 256>>>(x, pxp);

    cudaFuncSetAttribute(rnn_mma, cudaFuncAttributeMaxDynamicSharedMemorySize, SMEM_BYTES);
    rnn_mma<<<NCTA, 256, SMEM_BYTES>>>(out, Wh, Wx, Wo, pxp, phA, phf);
}

// round 11
// speedup vs baseline: 2.2604x; 1.0270x over previous
#include <cuda_runtime.h>
#include <cuda_bf16.h>
#include <cstdint>

#define B_    256
#define T_    512
#define IN_   64
#define H_    1024
#define OUT_  128
#define NCTA  128
#define NTHR  512
#define HBUF  (16 * 64 * 2 * 32)      // uint4s per h buffer: [mt][kc][hl][lane]
#define B_BYTES   139264              // 68 kc x 2048 B (frag-pair interleaved, hi|lo)
#define EXCH_OFF  B_BYTES             // 3 wk-partials x (4 wm x 2048 B)
#define SMEM_BYTES (B_BYTES + 3 * 8192)

// ---------------- persistent device scratch ------------------------------
__device__ uint4 g_hA[2 * HBUF];                     // ping-pong h, A-frag packed
__device__ uint4 g_xp[(size_t)T_ * 16 * 4 * 2 * 32]; // x, A-frag packed per t
__device__ float g_hf[B_ * H_];                      // final h, plain fp32
__device__ unsigned g_bar_count;
__device__ volatile unsigned g_bar_gen;

// ---------------- helpers -------------------------------------------------
__device__ __forceinline__ uint32_t smem_u32(const void* p) {
    uint32_t a;
    asm("{ .reg .u64 t; cvta.to.shared.u64 t, %1; cvt.u32.u64 %0, t; }"
        : "=r"(a) : "l"(p));
    return a;
}

__device__ __forceinline__ uint32_t pk(float a, float b) {
    __nv_bfloat162 t = __floats2bfloat162_rn(a, b);
    return *reinterpret_cast<uint32_t*>(&t);
}

__device__ __forceinline__ void lds128(uint32_t* r, uint32_t a) {
    asm("ld.shared.v4.b32 {%0,%1,%2,%3}, [%4];"
        : "=r"(r[0]), "=r"(r[1]), "=r"(r[2]), "=r"(r[3]) : "r"(a));
}

__device__ __forceinline__ void mma16816(float* c, const uint32_t* a, const uint32_t* b) {
    asm("mma.sync.aligned.m16n8k16.row.col.f32.bf16.bf16.f32 "
        "{%0,%1,%2,%3}, {%4,%5,%6,%7}, {%8,%9}, {%0,%1,%2,%3};"
        : "+f"(c[0]), "+f"(c[1]), "+f"(c[2]), "+f"(c[3])
        : "r"(a[0]), "r"(a[1]), "r"(a[2]), "r"(a[3]), "r"(b[0]), "r"(b[1]));
}

__device__ __forceinline__ void grid_sync() {
    __syncthreads();
    if (threadIdx.x == 0) {
        __threadfence();
        unsigned gen = g_bar_gen;
        if (atomicAdd(&g_bar_count, 1u) == NCTA - 1u) {
            atomicExch(&g_bar_count, 0u);
            __threadfence();
            g_bar_gen = gen + 1u;
        } else {
            while (g_bar_gen == gen) { }
        }
        __threadfence();
    }
    __syncthreads();
}

// ---------------- pack x into A-fragment layout (one-time) ----------------
__global__ void pack_x(const float* __restrict__ x, uint4* __restrict__ xp) {
    int id = blockIdx.x * (blockDim.x >> 5) + (threadIdx.x >> 5);
    int l  = threadIdx.x & 31;
    if (id >= T_ * 16 * 4) return;
    int t = id >> 6, mt = (id >> 2) & 15, kcx = id & 3;
    int b0 = mt * 16 + (l >> 2), b1 = b0 + 8;
    int i0 = kcx * 16 + 2 * (l & 3);
    const float* x0 = x + ((size_t)b0 * T_ + t) * IN_;
    const float* x1 = x + ((size_t)b1 * T_ + t) * IN_;
    float v00 = x0[i0], v01 = x0[i0 + 1], v02 = x0[i0 + 8], v03 = x0[i0 + 9];
    float v10 = x1[i0], v11 = x1[i0 + 1], v12 = x1[i0 + 8], v13 = x1[i0 + 9];
    uint4 hi4, lo4;
    hi4.x = pk(v00, v01); hi4.y = pk(v10, v11);
    hi4.z = pk(v02, v03); hi4.w = pk(v12, v13);
    float r00 = v00 - __bfloat162float(__float2bfloat16(v00));
    float r01 = v01 - __bfloat162float(__float2bfloat16(v01));
    float r02 = v02 - __bfloat162float(__float2bfloat16(v02));
    float r03 = v03 - __bfloat162float(__float2bfloat16(v03));
    float r10 = v10 - __bfloat162float(__float2bfloat16(v10));
    float r11 = v11 - __bfloat162float(__float2bfloat16(v11));
    float r12 = v12 - __bfloat162float(__float2bfloat16(v12));
    float r13 = v13 - __bfloat162float(__float2bfloat16(v13));
    lo4.x = pk(r00, r01); lo4.y = pk(r10, r11);
    lo4.z = pk(r02, r03); lo4.w = pk(r12, r13);
    size_t base = (size_t)id * 64 + l;
    xp[base] = hi4;
    xp[base + 32] = lo4;
}

// ---------------- persistent mma.sync RNN --------------------------------
// 128 CTAs x 512 threads (16 warps = wm(4) x wk(4)). CTA tile M64 x N32.
// Warp (wm, wk): full n32, K chunks [wk*17, wk*17+17). Every A fragment
// loaded by exactly ONE warp. 4 warps/SMSP hide issue/memory latency.
// wk partials combined once per step via 24KB smem exchange.
__global__ void __launch_bounds__(NTHR, 1) rnn_mma(
    float* __restrict__ out, const float* __restrict__ Wh,
    const float* __restrict__ Wx, const float* __restrict__ Wo,
    const uint4* __restrict__ xp, uint4* __restrict__ hA,
    float* __restrict__ hf)
{
    extern __shared__ __align__(16) uint8_t smem[];
    const int tid = threadIdx.x, l = tid & 31;
    const int wid = tid >> 5;
    const int wm = wid & 3, wk = wid >> 2;     // wk 0..3: one per SMSP pair slot
    const int bid = blockIdx.x;
    const int m0 = (bid >> 5) << 6;            // batch tile: 4 x 64
    const int n0 = (bid & 31) << 5;            // hidden tile: 32 x 32
    const uint32_t sB = smem_u32(smem);

    // ---- one-time: pack B slice (rows n0..n0+31 of [Wh | Wx]) into smem ----
    // per kc (2048B): hi [frpair0 512 | frpair1 512], lo at +1024.
    for (int e = tid; e < 32 * 1088; e += NTHR) {
        int nl = e / 1088, k = e - nl * 1088;
        float v = (k < 1024) ? Wh[(size_t)(n0 + nl) * 1024 + k]
                             : Wx[(size_t)(n0 + nl) * 64 + (k - 1024)];
        __nv_bfloat16 h = __float2bfloat16(v);
        __nv_bfloat16 lo = __float2bfloat16(v - __bfloat162float(h));
        int kc = k >> 4, fr = nl >> 3, frp = fr >> 1, f01 = fr & 1;
        int lane = ((nl & 7) << 2) | ((k & 7) >> 1);
        int w = (k >> 3) & 1, hb = k & 1;
        uint32_t off = (uint32_t)kc * 2048 + frp * 512 + lane * 16 + f01 * 8 + w * 4 + hb * 2;
        *reinterpret_cast<__nv_bfloat16*>(smem + off)        = h;
        *reinterpret_cast<__nv_bfloat16*>(smem + off + 1024) = lo;
    }
    // zero h buffer 0 (h_{-1} = 0)
    {
        uint4 z = make_uint4(0, 0, 0, 0);
        for (int i = bid * NTHR + tid; i < HBUF; i += NCTA * NTHR) hA[i] = z;
    }
    grid_sync();

    const int mtg   = (m0 >> 4) + wm;          // this warp's global m16 tile
    const int kcd0  = (n0 >> 4);               // epilogue dest kc (2 chunks for n32)
    const int kbase = wk * 17;                 // this warp's first K chunk

    for (int t = 0; t < T_; ++t) {
        const uint4* __restrict__ hcur = hA + (size_t)(t & 1) * HBUF;
        uint4* __restrict__ hnxt       = hA + (size_t)((t + 1) & 1) * HBUF;
        const uint4* __restrict__ xpt  = xp + (size_t)t * 4096;

        float chh[4][4], chl_[4][4], clh[4][4];
#pragma unroll
        for (int f = 0; f < 4; ++f)
#pragma unroll
            for (int j = 0; j < 4; ++j)
                chh[f][j] = chl_[f][j] = clh[f][j] = 0.f;

        auto ablk = [&](int kc) -> const uint4* {
            return (kc < 64)
                ? hcur + ((size_t)(mtg * 64 + kc) * 2) * 32 + l
                : xpt  + ((size_t)(mtg * 4 + (kc - 64)) * 2) * 32 + l;
        };

        uint4 sAh[4], sAl[4];
#pragma unroll
        for (int p = 0; p < 4; ++p) {
            const uint4* ap = ablk(kbase + p);
            sAh[p] = ap[0];
            sAl[p] = ap[32];
        }

        auto chunk = [&](int kc, const uint4& Ah, const uint4& Al) {
            const uint32_t ba = sB + (uint32_t)kc * 2048 + l * 16;
            uint32_t bh[8], bl[8];
            lds128(bh,     ba);         lds128(bh + 4, ba + 512);
            lds128(bl,     ba + 1024);  lds128(bl + 4, ba + 1536);
            const uint32_t* ah = reinterpret_cast<const uint32_t*>(&Ah);
            const uint32_t* al = reinterpret_cast<const uint32_t*>(&Al);
            mma16816(chh[0],  ah, bh);      mma16816(chh[1],  ah, bh + 2);
            mma16816(chh[2],  ah, bh + 4);  mma16816(chh[3],  ah, bh + 6);
            mma16816(chl_[0], ah, bl);      mma16816(chl_[1], ah, bl + 2);
            mma16816(chl_[2], ah, bl + 4);  mma16816(chl_[3], ah, bl + 6);
            mma16816(clh[0],  al, bh);      mma16816(clh[1],  al, bh + 2);
            mma16816(clh[2],  al, bh + 4);  mma16816(clh[3],  al, bh + 6);
        };

        // ---- 16 chunks under unroll-4 (slot i&3 static), then 1 peeled ------
#pragma unroll 4
        for (int i = 0; i < 16; ++i) {
            const int s = i & 3;
            chunk(kbase + i, sAh[s], sAl[s]);
            if (i <= 12) {                     // prefetch chunk i+4 (<= 16)
                const uint4* ap = ablk(kbase + i + 4);
                sAh[s] = ap[0];
                sAl[s] = ap[32];
            }
        }
        chunk(kbase + 16, sAh[0], sAl[0]);     // chunk 16 sits in slot 0

        // ---- combine wk quarters: wk>0 -> smem, wk0 adds, relu, split -------
        if (wk > 0) {
            const uint32_t eo = EXCH_OFF + (uint32_t)(wk - 1) * 8192 + wm * 2048 + l * 16;
#pragma unroll
            for (int f = 0; f < 4; ++f) {
                float4 s4 = make_float4(
                    chh[f][0] + chl_[f][0] + clh[f][0],
                    chh[f][1] + chl_[f][1] + clh[f][1],
                    chh[f][2] + chl_[f][2] + clh[f][2],
                    chh[f][3] + chl_[f][3] + clh[f][3]);
                *reinterpret_cast<float4*>(smem + eo + f * 512) = s4;
            }
        }
        __syncthreads();
        if (wk == 0) {
            float v[4][4], r[4][4];
#pragma unroll
            for (int f = 0; f < 4; ++f) {
                float s0 = chh[f][0] + chl_[f][0] + clh[f][0];
                float s1 = chh[f][1] + chl_[f][1] + clh[f][1];
                float s2 = chh[f][2] + chl_[f][2] + clh[f][2];
                float s3 = chh[f][3] + chl_[f][3] + clh[f][3];
#pragma unroll
                for (int q = 0; q < 3; ++q) {
                    float4 p = *reinterpret_cast<const float4*>(
                        smem + EXCH_OFF + q * 8192 + wm * 2048 + f * 512 + l * 16);
                    s0 += p.x; s1 += p.y; s2 += p.z; s3 += p.w;
                }
                s0 = fmaxf(s0, 0.f); s1 = fmaxf(s1, 0.f);
                s2 = fmaxf(s2, 0.f); s3 = fmaxf(s3, 0.f);
                v[f][0] = s0; v[f][1] = s1; v[f][2] = s2; v[f][3] = s3;
                r[f][0] = s0 - __bfloat162float(__float2bfloat16(s0));
                r[f][1] = s1 - __bfloat162float(__float2bfloat16(s1));
                r[f][2] = s2 - __bfloat162float(__float2bfloat16(s2));
                r[f][3] = s3 - __bfloat162float(__float2bfloat16(s3));
            }
            // frags (0,1) -> dest chunk kcd0 ; frags (2,3) -> kcd0+1
#pragma unroll
            for (int cpair = 0; cpair < 2; ++cpair) {
                const int f = cpair * 2;
                uint4 hi4, lo4;
                hi4.x = pk(v[f][0], v[f][1]);         hi4.y = pk(v[f][2], v[f][3]);
                hi4.z = pk(v[f + 1][0], v[f + 1][1]); hi4.w = pk(v[f + 1][2], v[f + 1][3]);
                lo4.x = pk(r[f][0], r[f][1]);         lo4.y = pk(r[f][2], r[f][3]);
                lo4.z = pk(r[f + 1][0], r[f + 1][1]); lo4.w = pk(r[f + 1][2], r[f + 1][3]);
                uint4* dst = hnxt + ((size_t)(mtg * 64 + kcd0 + cpair) * 2) * 32 + l;
                dst[0]  = hi4;
                dst[32] = lo4;
            }
            if (t == T_ - 1) {
                int r0 = mtg * 16 + (l >> 2);
#pragma unroll
                for (int f = 0; f < 4; ++f) {
                    int c0 = n0 + f * 8 + 2 * (l & 3);
                    *(float2*)&hf[(size_t)r0 * H_ + c0]       = make_float2(v[f][0], v[f][1]);
                    *(float2*)&hf[(size_t)(r0 + 8) * H_ + c0] = make_float2(v[f][2], v[f][3]);
                }
            }
        }
        grid_sync();
    }

    // ---- final: out[m][o] = sum_k h[m][k] * Wo[o][k]; 2 batch rows per CTA ---
    {
        float* sw = (float*)smem;                 // [128][129] padded
        float* sh = (float*)smem + 128 * 129;     // [2][1024]
        const int m = bid * 2;
        const int half = (tid >> 7) & 1, o = tid & 127;
        for (int i = tid; i < 2 * H_; i += NTHR)
            sh[i] = hf[(size_t)(m + (i >> 10)) * H_ + (i & 1023)];
        float acc = 0.f;
        for (int k0 = 0; k0 < H_; k0 += 128) {
            __syncthreads();
            for (int i = tid; i < 128 * 128; i += NTHR) {
                int oo = i >> 7, kk = i & 127;
                sw[oo * 129 + kk] = Wo[(size_t)oo * H_ + k0 + kk];
            }
            __syncthreads();
            if (tid < 256) {
#pragma unroll 8
                for (int kk = 0; kk < 128; ++kk)
                    acc = fmaf(sh[half * H_ + k0 + kk], sw[o * 129 + kk], acc);
            }
        }
        if (tid < 256)
            out[(size_t)(m + half) * OUT_ + o] = acc;
    }
}

// ---------------- launch --------------------------------------------------
extern "C" void kernel_launch(void* const* d_in, const int* in_sizes, int n_in,
                              void* d_out, int out_size) {
    (void)in_sizes; (void)n_in; (void)out_size;
    const float* x  = (const float*)d_in[0];
    const float* Wh = (const float*)d_in[1];
    const float* Wx = (const float*)d_in[2];
    const float* Wo = (const float*)d_in[3];
    float* out = (float*)d_out;

    uint4 *phA, *pxp;
    float* phf;
    cudaGetSymbolAddress((void**)&phA, g_hA);
    cudaGetSymbolAddress((void**)&pxp, g_xp);
    cudaGetSymbolAddress((void**)&phf, g_hf);

    pack_x<<<4096, 256>>>(x, pxp);

    cudaFuncSetAttribute(rnn_mma, cudaFuncAttributeMaxDynamicSharedMemorySize, SMEM_BYTES);
    rnn_mma<<<NCTA, NTHR, SMEM_BYTES>>>(out, Wh, Wx, Wo, pxp, phA, phf);
}

// round 12
// speedup vs baseline: 2.2983x; 1.0168x over previous
#include <cuda_runtime.h>
#include <cuda_bf16.h>
#include <cstdint>

#define B_    256
#define T_    512
#define IN_   64
#define H_    1024
#define OUT_  128
#define NCTA  128
#define NTHR  512
#define HBUF  (16 * 64 * 2 * 32)      // uint4s per h buffer: [mt][kc][hl][lane]
#define B_BYTES   139264              // 68 kc x 2048 B (frag-pair interleaved, hi|lo)
#define EXCH_OFF  B_BYTES             // 3 wk-partials x (4 wm x 2048 B)
#define SMEM_BYTES (B_BYTES + 3 * 8192)

// ---------------- persistent device scratch ------------------------------
__device__ uint4 g_hA[2 * HBUF];                     // ping-pong h, A-frag packed
__device__ uint4 g_xp[(size_t)T_ * 16 * 4 * 2 * 32]; // x, A-frag packed per t
__device__ float g_hf[B_ * H_];                      // final h, plain fp32
__device__ unsigned g_bar_count;                     // one-time init barrier
__device__ volatile unsigned g_bar_gen;
// per-m-group step barriers, each counter/gen on its own 128B line
__device__ __align__(128) unsigned g_gcnt[4 * 32];
__device__ __align__(128) volatile unsigned g_ggen[4 * 32];

// ---------------- helpers -------------------------------------------------
__device__ __forceinline__ uint32_t smem_u32(const void* p) {
    uint32_t a;
    asm("{ .reg .u64 t; cvta.to.shared.u64 t, %1; cvt.u32.u64 %0, t; }"
        : "=r"(a) : "l"(p));
    return a;
}

__device__ __forceinline__ uint32_t pk(float a, float b) {
    __nv_bfloat162 t = __floats2bfloat162_rn(a, b);
    return *reinterpret_cast<uint32_t*>(&t);
}

__device__ __forceinline__ void lds128(uint32_t* r, uint32_t a) {
    asm("ld.shared.v4.b32 {%0,%1,%2,%3}, [%4];"
        : "=r"(r[0]), "=r"(r[1]), "=r"(r[2]), "=r"(r[3]) : "r"(a));
}

__device__ __forceinline__ void mma16816(float* c, const uint32_t* a, const uint32_t* b) {
    asm("mma.sync.aligned.m16n8k16.row.col.f32.bf16.bf16.f32 "
        "{%0,%1,%2,%3}, {%4,%5,%6,%7}, {%8,%9}, {%0,%1,%2,%3};"
        : "+f"(c[0]), "+f"(c[1]), "+f"(c[2]), "+f"(c[3])
        : "r"(a[0]), "r"(a[1]), "r"(a[2]), "r"(a[3]), "r"(b[0]), "r"(b[1]));
}

// one-time full-grid barrier (init only)
__device__ __forceinline__ void grid_sync_all() {
    __syncthreads();
    if (threadIdx.x == 0) {
        __threadfence();
        unsigned gen = g_bar_gen;
        if (atomicAdd(&g_bar_count, 1u) == NCTA - 1u) {
            atomicExch(&g_bar_count, 0u);
            __threadfence();
            g_bar_gen = gen + 1u;
        } else {
            while (g_bar_gen == gen) { }
        }
        __threadfence();
    }
    __syncthreads();
}

// per-step barrier over the 32 CTAs of one m-group
__device__ __forceinline__ void group_sync(int g) {
    __syncthreads();
    if (threadIdx.x == 0) {
        __threadfence();
        const int s = g * 32;
        unsigned gen = g_ggen[s];
        if (atomicAdd(&g_gcnt[s], 1u) == 31u) {
            atomicExch(&g_gcnt[s], 0u);
            __threadfence();
            g_ggen[s] = gen + 1u;
        } else {
            while (g_ggen[s] == gen) { }
        }
        __threadfence();
    }
    __syncthreads();
}

// ---------------- pack x into A-fragment layout (one-time) ----------------
__global__ void pack_x(const float* __restrict__ x, uint4* __restrict__ xp) {
    int id = blockIdx.x * (blockDim.x >> 5) + (threadIdx.x >> 5);
    int l  = threadIdx.x & 31;
    if (id >= T_ * 16 * 4) return;
    int t = id >> 6, mt = (id >> 2) & 15, kcx = id & 3;
    int b0 = mt * 16 + (l >> 2), b1 = b0 + 8;
    int i0 = kcx * 16 + 2 * (l & 3);
    const float* x0 = x + ((size_t)b0 * T_ + t) * IN_;
    const float* x1 = x + ((size_t)b1 * T_ + t) * IN_;
    float v00 = x0[i0], v01 = x0[i0 + 1], v02 = x0[i0 + 8], v03 = x0[i0 + 9];
    float v10 = x1[i0], v11 = x1[i0 + 1], v12 = x1[i0 + 8], v13 = x1[i0 + 9];
    uint4 hi4, lo4;
    hi4.x = pk(v00, v01); hi4.y = pk(v10, v11);
    hi4.z = pk(v02, v03); hi4.w = pk(v12, v13);
    float r00 = v00 - __bfloat162float(__float2bfloat16(v00));
    float r01 = v01 - __bfloat162float(__float2bfloat16(v01));
    float r02 = v02 - __bfloat162float(__float2bfloat16(v02));
    float r03 = v03 - __bfloat162float(__float2bfloat16(v03));
    float r10 = v10 - __bfloat162float(__float2bfloat16(v10));
    float r11 = v11 - __bfloat162float(__float2bfloat16(v11));
    float r12 = v12 - __bfloat162float(__float2bfloat16(v12));
    float r13 = v13 - __bfloat162float(__float2bfloat16(v13));
    lo4.x = pk(r00, r01); lo4.y = pk(r10, r11);
    lo4.z = pk(r02, r03); lo4.w = pk(r12, r13);
    size_t base = (size_t)id * 64 + l;
    xp[base] = hi4;
    xp[base + 32] = lo4;
}

// ---------------- persistent mma.sync RNN --------------------------------
// 128 CTAs x 512 threads (16 warps = wm(4) x wk(4)). CTA tile M64 x N32.
// Warp (wm, wk): full n32, K chunks [wk*17, wk*17+17). Per-step sync is
// scoped to the 32 CTAs of the CTA's m-group (groups are independent).
__global__ void __launch_bounds__(NTHR, 1) rnn_mma(
    float* __restrict__ out, const float* __restrict__ Wh,
    const float* __restrict__ Wx, const float* __restrict__ Wo,
    const uint4* __restrict__ xp, uint4* __restrict__ hA,
    float* __restrict__ hf)
{
    extern __shared__ __align__(16) uint8_t smem[];
    const int tid = threadIdx.x, l = tid & 31;
    const int wid = tid >> 5;
    const int wm = wid & 3, wk = wid >> 2;
    const int bid = blockIdx.x;
    const int grp = bid >> 5;                  // m-group (4 groups x 32 CTAs)
    const int m0 = grp << 6;                   // batch tile: 4 x 64
    const int n0 = (bid & 31) << 5;            // hidden tile: 32 x 32
    const uint32_t sB = smem_u32(smem);

    // ---- one-time: pack B slice (rows n0..n0+31 of [Wh | Wx]) into smem ----
    for (int e = tid; e < 32 * 1088; e += NTHR) {
        int nl = e / 1088, k = e - nl * 1088;
        float v = (k < 1024) ? Wh[(size_t)(n0 + nl) * 1024 + k]
                             : Wx[(size_t)(n0 + nl) * 64 + (k - 1024)];
        __nv_bfloat16 h = __float2bfloat16(v);
        __nv_bfloat16 lo = __float2bfloat16(v - __bfloat162float(h));
        int kc = k >> 4, fr = nl >> 3, frp = fr >> 1, f01 = fr & 1;
        int lane = ((nl & 7) << 2) | ((k & 7) >> 1);
        int w = (k >> 3) & 1, hb = k & 1;
        uint32_t off = (uint32_t)kc * 2048 + frp * 512 + lane * 16 + f01 * 8 + w * 4 + hb * 2;
        *reinterpret_cast<__nv_bfloat16*>(smem + off)        = h;
        *reinterpret_cast<__nv_bfloat16*>(smem + off + 1024) = lo;
    }
    // zero h buffer 0 (h_{-1} = 0)
    {
        uint4 z = make_uint4(0, 0, 0, 0);
        for (int i = bid * NTHR + tid; i < HBUF; i += NCTA * NTHR) hA[i] = z;
    }
    grid_sync_all();

    const int mtg   = (m0 >> 4) + wm;          // this warp's global m16 tile
    const int kcd0  = (n0 >> 4);               // epilogue dest kc (2 chunks)
    const int kbase = wk * 17;                 // this warp's first K chunk

    for (int t = 0; t < T_; ++t) {
        const uint4* __restrict__ hcur = hA + (size_t)(t & 1) * HBUF;
        uint4* __restrict__ hnxt       = hA + (size_t)((t + 1) & 1) * HBUF;
        const uint4* __restrict__ xpt  = xp + (size_t)t * 4096;

        float chh[4][4], chl_[4][4], clh[4][4];
#pragma unroll
        for (int f = 0; f < 4; ++f)
#pragma unroll
            for (int j = 0; j < 4; ++j)
                chh[f][j] = chl_[f][j] = clh[f][j] = 0.f;

        auto ablk = [&](int kc) -> const uint4* {
            return (kc < 64)
                ? hcur + ((size_t)(mtg * 64 + kc) * 2) * 32 + l
                : xpt  + ((size_t)(mtg * 4 + (kc - 64)) * 2) * 32 + l;
        };

        uint4 sAh[4], sAl[4];
#pragma unroll
        for (int p = 0; p < 4; ++p) {
            const uint4* ap = ablk(kbase + p);
            sAh[p] = ap[0];
            sAl[p] = ap[32];
        }

        auto chunk = [&](int kc, const uint4& Ah, const uint4& Al) {
            const uint32_t ba = sB + (uint32_t)kc * 2048 + l * 16;
            uint32_t bh[8], bl[8];
            lds128(bh,     ba);         lds128(bh + 4, ba + 512);
            lds128(bl,     ba + 1024);  lds128(bl + 4, ba + 1536);
            const uint32_t* ah = reinterpret_cast<const uint32_t*>(&Ah);
            const uint32_t* al = reinterpret_cast<const uint32_t*>(&Al);
            mma16816(chh[0],  ah, bh);      mma16816(chh[1],  ah, bh + 2);
            mma16816(chh[2],  ah, bh + 4);  mma16816(chh[3],  ah, bh + 6);
            mma16816(chl_[0], ah, bl);      mma16816(chl_[1], ah, bl + 2);
            mma16816(chl_[2], ah, bl + 4);  mma16816(chl_[3], ah, bl + 6);
            mma16816(clh[0],  al, bh);      mma16816(clh[1],  al, bh + 2);
            mma16816(clh[2],  al, bh + 4);  mma16816(clh[3],  al, bh + 6);
        };

        // ---- 16 chunks under unroll-4 (slot i&3 static), then 1 peeled ------
#pragma unroll 4
        for (int i = 0; i < 16; ++i) {
            const int s = i & 3;
            chunk(kbase + i, sAh[s], sAl[s]);
            if (i <= 12) {
                const uint4* ap = ablk(kbase + i + 4);
                sAh[s] = ap[0];
                sAl[s] = ap[32];
            }
        }
        chunk(kbase + 16, sAh[0], sAl[0]);

        // ---- combine wk quarters: wk>0 -> smem, wk0 adds, relu, split -------
        if (wk > 0) {
            const uint32_t eo = EXCH_OFF + (uint32_t)(wk - 1) * 8192 + wm * 2048 + l * 16;
#pragma unroll
            for (int f = 0; f < 4; ++f) {
                float4 s4 = make_float4(
                    chh[f][0] + chl_[f][0] + clh[f][0],
                    chh[f][1] + chl_[f][1] + clh[f][1],
                    chh[f][2] + chl_[f][2] + clh[f][2],
                    chh[f][3] + chl_[f][3] + clh[f][3]);
                *reinterpret_cast<float4*>(smem + eo + f * 512) = s4;
            }
        }
        __syncthreads();
        if (wk == 0) {
            float v[4][4], r[4][4];
#pragma unroll
            for (int f = 0; f < 4; ++f) {
                float s0 = chh[f][0] + chl_[f][0] + clh[f][0];
                float s1 = chh[f][1] + chl_[f][1] + clh[f][1];
                float s2 = chh[f][2] + chl_[f][2] + clh[f][2];
                float s3 = chh[f][3] + chl_[f][3] + clh[f][3];
#pragma unroll
                for (int q = 0; q < 3; ++q) {
                    float4 p = *reinterpret_cast<const float4*>(
                        smem + EXCH_OFF + q * 8192 + wm * 2048 + f * 512 + l * 16);
                    s0 += p.x; s1 += p.y; s2 += p.z; s3 += p.w;
                }
                s0 = fmaxf(s0, 0.f); s1 = fmaxf(s1, 0.f);
                s2 = fmaxf(s2, 0.f); s3 = fmaxf(s3, 0.f);
                v[f][0] = s0; v[f][1] = s1; v[f][2] = s2; v[f][3] = s3;
                r[f][0] = s0 - __bfloat162float(__float2bfloat16(s0));
                r[f][1] = s1 - __bfloat162float(__float2bfloat16(s1));
                r[f][2] = s2 - __bfloat162float(__float2bfloat16(s2));
                r[f][3] = s3 - __bfloat162float(__float2bfloat16(s3));
            }
#pragma unroll
            for (int cpair = 0; cpair < 2; ++cpair) {
                const int f = cpair * 2;
                uint4 hi4, lo4;
                hi4.x = pk(v[f][0], v[f][1]);         hi4.y = pk(v[f][2], v[f][3]);
                hi4.z = pk(v[f + 1][0], v[f + 1][1]); hi4.w = pk(v[f + 1][2], v[f + 1][3]);
                lo4.x = pk(r[f][0], r[f][1]);         lo4.y = pk(r[f][2], r[f][3]);
                lo4.z = pk(r[f + 1][0], r[f + 1][1]); lo4.w = pk(r[f + 1][2], r[f + 1][3]);
                uint4* dst = hnxt + ((size_t)(mtg * 64 + kcd0 + cpair) * 2) * 32 + l;
                dst[0]  = hi4;
                dst[32] = lo4;
            }
            if (t == T_ - 1) {
                int r0 = mtg * 16 + (l >> 2);
#pragma unroll
                for (int f = 0; f < 4; ++f) {
                    int c0 = n0 + f * 8 + 2 * (l & 3);
                    *(float2*)&hf[(size_t)r0 * H_ + c0]       = make_float2(v[f][0], v[f][1]);
                    *(float2*)&hf[(size_t)(r0 + 8) * H_ + c0] = make_float2(v[f][2], v[f][3]);
                }
            }
        }
        group_sync(grp);
    }

    // ---- final: out[m][o] = sum_k h[m][k] * Wo[o][k]; 2 batch rows per CTA ---
    // (rows bid*2, bid*2+1 are in this CTA's own m-group: (bid*2)>>6 == grp)
    {
        float* sw = (float*)smem;                 // [128][129] padded
        float* sh = (float*)smem + 128 * 129;     // [2][1024]
        const int m = bid * 2;
        const int half = (tid >> 7) & 1, o = tid & 127;
        for (int i = tid; i < 2 * H_; i += NTHR)
            sh[i] = hf[(size_t)(m + (i >> 10)) * H_ + (i & 1023)];
        float acc = 0.f;
        for (int k0 = 0; k0 < H_; k0 += 128) {
            __syncthreads();
            for (int i = tid; i < 128 * 128; i += NTHR) {
                int oo = i >> 7, kk = i & 127;
                sw[oo * 129 + kk] = Wo[(size_t)oo * H_ + k0 + kk];
            }
            __syncthreads();
            if (tid < 256) {
#pragma unroll 8
                for (int kk = 0; kk < 128; ++kk)
                    acc = fmaf(sh[half * H_ + k0 + kk], sw[o * 129 + kk], acc);
            }
        }
        if (tid < 256)
            out[(size_t)(m + half) * OUT_ + o] = acc;
    }
}

// ---------------- launch --------------------------------------------------
extern "C" void kernel_launch(void* const* d_in, const int* in_sizes, int n_in,
                              void* d_out, int out_size) {
    (void)in_sizes; (void)n_in; (void)out_size;
    const float* x  = (const float*)d_in[0];
    const float* Wh = (const float*)d_in[1];
    const float* Wx = (const float*)d_in[2];
    const float* Wo = (const float*)d_in[3];
    float* out = (float*)d_out;

    uint4 *phA, *pxp;
    float* phf;
    cudaGetSymbolAddress((void**)&phA, g_hA);
    cudaGetSymbolAddress((void**)&pxp, g_xp);
    cudaGetSymbolAddress((void**)&phf, g_hf);

    pack_x<<<4096, 256>>>(x, pxp);

    cudaFuncSetAttribute(rnn_mma, cudaFuncAttributeMaxDynamicSharedMemorySize, SMEM_BYTES);
    rnn_mma<<<NCTA, NTHR, SMEM_BYTES>>>(out, Wh, Wx, Wo, pxp, phA, phf);
}

// round 16
// speedup vs baseline: 2.3971x; 1.0430x over previous
#include <cuda_runtime.h>
#include <cuda_bf16.h>
#include <cstdint>

#define B_    256
#define T_    512
#define IN_   64
#define H_    1024
#define OUT_  128
#define NCTA  128
#define NTHR  512
#define HBUF  (16 * 64 * 2 * 32)      // uint4s per h buffer: [mt][kc][hl][lane]
#define B_BYTES   139264              // 68 kc x 2048 B (frag-pair interleaved, hi|lo)
#define EXCH_OFF  B_BYTES             // 3 wk-partials x (4 wm x 2048 B)
#define SMEM_BYTES (B_BYTES + 3 * 8192)

// ---------------- persistent device scratch ------------------------------
__device__ uint4 g_hA[2 * HBUF];                     // ping-pong h, A-frag packed
__device__ uint4 g_xp[(size_t)T_ * 16 * 4 * 2 * 32]; // x, A-frag packed per t
__device__ float g_hf[B_ * H_];                      // final h, plain fp32
__device__ unsigned g_bar_count;                     // one-time init barrier
__device__ volatile unsigned g_bar_gen;
// per-m-group step barriers, each counter/gen on its own 128B line
__device__ __align__(128) unsigned g_gcnt[4 * 32];
__device__ __align__(128) volatile unsigned g_ggen[4 * 32];

// ---------------- helpers -------------------------------------------------
__device__ __forceinline__ uint32_t smem_u32(const void* p) {
    uint32_t a;
    asm("{ .reg .u64 t; cvta.to.shared.u64 t, %1; cvt.u32.u64 %0, t; }"
        : "=r"(a) : "l"(p));
    return a;
}

__device__ __forceinline__ uint32_t pk(float a, float b) {
    __nv_bfloat162 t = __floats2bfloat162_rn(a, b);
    return *reinterpret_cast<uint32_t*>(&t);
}

__device__ __forceinline__ void lds128(uint32_t* r, uint32_t a) {
    asm("ld.shared.v4.b32 {%0,%1,%2,%3}, [%4];"
        : "=r"(r[0]), "=r"(r[1]), "=r"(r[2]), "=r"(r[3]) : "r"(a));
}

__device__ __forceinline__ void mma16816(float* c, const uint32_t* a, const uint32_t* b) {
    asm("mma.sync.aligned.m16n8k16.row.col.f32.bf16.bf16.f32 "
        "{%0,%1,%2,%3}, {%4,%5,%6,%7}, {%8,%9}, {%0,%1,%2,%3};"
        : "+f"(c[0]), "+f"(c[1]), "+f"(c[2]), "+f"(c[3])
        : "r"(a[0]), "r"(a[1]), "r"(a[2]), "r"(a[3]), "r"(b[0]), "r"(b[1]));
}

// one-time full-grid barrier (init only)
__device__ __forceinline__ void grid_sync_all() {
    __syncthreads();
    if (threadIdx.x == 0) {
        __threadfence();
        unsigned gen = g_bar_gen;
        if (atomicAdd(&g_bar_count, 1u) == NCTA - 1u) {
            atomicExch(&g_bar_count, 0u);
            __threadfence();
            g_bar_gen = gen + 1u;
        } else {
            while (g_bar_gen == gen) { }
        }
        __threadfence();
    }
    __syncthreads();
}

// per-step barrier over the 32 CTAs of one m-group
__device__ __forceinline__ void group_sync(int g) {
    __syncthreads();
    if (threadIdx.x == 0) {
        __threadfence();
        const int s = g * 32;
        unsigned gen = g_ggen[s];
        if (atomicAdd(&g_gcnt[s], 1u) == 31u) {
            atomicExch(&g_gcnt[s], 0u);
            __threadfence();
            g_ggen[s] = gen + 1u;
        } else {
            while (g_ggen[s] == gen) { }
        }
        __threadfence();
    }
    __syncthreads();
}

// ---------------- pack x into A-fragment layout (one-time) ----------------
__global__ void pack_x(const float* __restrict__ x, uint4* __restrict__ xp) {
    int id = blockIdx.x * (blockDim.x >> 5) + (threadIdx.x >> 5);
    int l  = threadIdx.x & 31;
    if (id >= T_ * 16 * 4) return;
    int t = id >> 6, mt = (id >> 2) & 15, kcx = id & 3;
    int b0 = mt * 16 + (l >> 2), b1 = b0 + 8;
    int i0 = kcx * 16 + 2 * (l & 3);
    const float* x0 = x + ((size_t)b0 * T_ + t) * IN_;
    const float* x1 = x + ((size_t)b1 * T_ + t) * IN_;
    float v00 = x0[i0], v01 = x0[i0 + 1], v02 = x0[i0 + 8], v03 = x0[i0 + 9];
    float v10 = x1[i0], v11 = x1[i0 + 1], v12 = x1[i0 + 8], v13 = x1[i0 + 9];
    uint4 hi4, lo4;
    hi4.x = pk(v00, v01); hi4.y = pk(v10, v11);
    hi4.z = pk(v02, v03); hi4.w = pk(v12, v13);
    float r00 = v00 - __bfloat162float(__float2bfloat16(v00));
    float r01 = v01 - __bfloat162float(__float2bfloat16(v01));
    float r02 = v02 - __bfloat162float(__float2bfloat16(v02));
    float r03 = v03 - __bfloat162float(__float2bfloat16(v03));
    float r10 = v10 - __bfloat162float(__float2bfloat16(v10));
    float r11 = v11 - __bfloat162float(__float2bfloat16(v11));
    float r12 = v12 - __bfloat162float(__float2bfloat16(v12));
    float r13 = v13 - __bfloat162float(__float2bfloat16(v13));
    lo4.x = pk(r00, r01); lo4.y = pk(r10, r11);
    lo4.z = pk(r02, r03); lo4.w = pk(r12, r13);
    size_t base = (size_t)id * 64 + l;
    xp[base] = hi4;
    xp[base + 32] = lo4;
}

// ---------------- persistent mma.sync RNN --------------------------------
// 128 CTAs x 512 threads (16 warps = wm(4) x wk(4)). CTA tile M64 x N32.
// Warp (wm, wk): full n32, h chunks [wk*16, wk*16+16) + x chunk 64+wk.
// The x chunk (barrier-independent) is computed FIRST, hiding the cold
// post-barrier L2 latency of the first h-A loads. Per-step sync scoped to
// the CTA's m-group (R12-proven).
__global__ void __launch_bounds__(NTHR, 1) rnn_mma(
    float* __restrict__ out, const float* __restrict__ Wh,
    const float* __restrict__ Wx, const float* __restrict__ Wo,
    const uint4* __restrict__ xp, uint4* __restrict__ hA,
    float* __restrict__ hf)
{
    extern __shared__ __align__(16) uint8_t smem[];
    const int tid = threadIdx.x, l = tid & 31;
    const int wid = tid >> 5;
    const int wm = wid & 3, wk = wid >> 2;
    const int bid = blockIdx.x;
    const int grp = bid >> 5;                  // m-group (4 groups x 32 CTAs)
    const int m0 = grp << 6;
    const int n0 = (bid & 31) << 5;            // hidden tile: 32 x 32
    const uint32_t sB = smem_u32(smem);

    // ---- one-time: pack B slice (rows n0..n0+31 of [Wh | Wx]) into smem ----
    for (int e = tid; e < 32 * 1088; e += NTHR) {
        int nl = e / 1088, k = e - nl * 1088;
        float v = (k < 1024) ? Wh[(size_t)(n0 + nl) * 1024 + k]
                             : Wx[(size_t)(n0 + nl) * 64 + (k - 1024)];
        __nv_bfloat16 h = __float2bfloat16(v);
        __nv_bfloat16 lo = __float2bfloat16(v - __bfloat162float(h));
        int kc = k >> 4, fr = nl >> 3, frp = fr >> 1, f01 = fr & 1;
        int lane = ((nl & 7) << 2) | ((k & 7) >> 1);
        int w = (k >> 3) & 1, hb = k & 1;
        uint32_t off = (uint32_t)kc * 2048 + frp * 512 + lane * 16 + f01 * 8 + w * 4 + hb * 2;
        *reinterpret_cast<__nv_bfloat16*>(smem + off)        = h;
        *reinterpret_cast<__nv_bfloat16*>(smem + off + 1024) = lo;
    }
    // zero h buffer 0 (h_{-1} = 0)
    {
        uint4 z = make_uint4(0, 0, 0, 0);
        for (int i = bid * NTHR + tid; i < HBUF; i += NCTA * NTHR) hA[i] = z;
    }
    grid_sync_all();

    const int mtg   = (m0 >> 4) + wm;          // this warp's global m16 tile
    const int kcd0  = (bid & 31) << 1 >> 1;    // (== bid&31 ... see below)
    const int kcd   = (n0 >> 4);               // epilogue dest kc (2 chunks)
    (void)kcd0;
    const int kbase = wk * 16;                 // this warp's first h chunk
    const int kcx   = 64 + wk;                 // this warp's x chunk

    for (int t = 0; t < T_; ++t) {
        const uint4* __restrict__ hcur = hA + (size_t)(t & 1) * HBUF;
        uint4* __restrict__ hnxt       = hA + (size_t)((t + 1) & 1) * HBUF;
        const uint4* __restrict__ xpt  = xp + (size_t)t * 4096;

        float chh[4][4], chl_[4][4], clh[4][4];
#pragma unroll
        for (int f = 0; f < 4; ++f)
#pragma unroll
            for (int j = 0; j < 4; ++j)
                chh[f][j] = chl_[f][j] = clh[f][j] = 0.f;

        // ---- prologue: issue first 4 h-A loads, then load + compute x ------
        uint4 sAh[4], sAl[4];
#pragma unroll
        for (int p = 0; p < 4; ++p) {
            const uint4* ap = hcur + ((size_t)(mtg * 64 + kbase + p) * 2) * 32 + l;
            sAh[p] = ap[0];
            sAl[p] = ap[32];
        }
        uint4 xAh, xAl;
        {
            const uint4* ap = xpt + ((size_t)(mtg * 4 + wk) * 2) * 32 + l;
            xAh = ap[0];
            xAl = ap[32];
        }

        auto chunk = [&](int kc, const uint4& Ah, const uint4& Al) {
            const uint32_t ba = sB + (uint32_t)kc * 2048 + l * 16;
            uint32_t bh[8], bl[8];
            lds128(bh,     ba);         lds128(bh + 4, ba + 512);
            lds128(bl,     ba + 1024);  lds128(bl + 4, ba + 1536);
            const uint32_t* ah = reinterpret_cast<const uint32_t*>(&Ah);
            const uint32_t* al = reinterpret_cast<const uint32_t*>(&Al);
            mma16816(chh[0],  ah, bh);      mma16816(chh[1],  ah, bh + 2);
            mma16816(chh[2],  ah, bh + 4);  mma16816(chh[3],  ah, bh + 6);
            mma16816(chl_[0], ah, bl);      mma16816(chl_[1], ah, bl + 2);
            mma16816(chl_[2], ah, bl + 4);  mma16816(chl_[3], ah, bl + 6);
            mma16816(clh[0],  al, bh);      mma16816(clh[1],  al, bh + 2);
            mma16816(clh[2],  al, bh + 4);  mma16816(clh[3],  al, bh + 6);
        };

        // x chunk first: covers the in-flight h-A cold loads
        chunk(kcx, xAh, xAl);

        // ---- 16 h chunks under unroll-4 (slot i&3 static) -------------------
#pragma unroll 4
        for (int i = 0; i < 16; ++i) {
            const int s = i & 3;
            chunk(kbase + i, sAh[s], sAl[s]);
            if (i < 12) {
                const uint4* ap = hcur + ((size_t)(mtg * 64 + kbase + i + 4) * 2) * 32 + l;
                sAh[s] = ap[0];
                sAl[s] = ap[32];
            }
        }

        // ---- combine wk quarters: wk>0 -> smem, wk0 adds, relu, split -------
        if (wk > 0) {
            const uint32_t eo = EXCH_OFF + (uint32_t)(wk - 1) * 8192 + wm * 2048 + l * 16;
#pragma unroll
            for (int f = 0; f < 4; ++f) {
                float4 s4 = make_float4(
                    chh[f][0] + chl_[f][0] + clh[f][0],
                    chh[f][1] + chl_[f][1] + clh[f][1],
                    chh[f][2] + chl_[f][2] + clh[f][2],
                    chh[f][3] + chl_[f][3] + clh[f][3]);
                *reinterpret_cast<float4*>(smem + eo + f * 512) = s4;
            }
        }
        __syncthreads();
        if (wk == 0) {
            float v[4][4], r[4][4];
#pragma unroll
            for (int f = 0; f < 4; ++f) {
                float s0 = chh[f][0] + chl_[f][0] + clh[f][0];
                float s1 = chh[f][1] + chl_[f][1] + clh[f][1];
                float s2 = chh[f][2] + chl_[f][2] + clh[f][2];
                float s3 = chh[f][3] + chl_[f][3] + clh[f][3];
#pragma unroll
                for (int q = 0; q < 3; ++q) {
                    float4 p = *reinterpret_cast<const float4*>(
                        smem + EXCH_OFF + q * 8192 + wm * 2048 + f * 512 + l * 16);
                    s0 += p.x; s1 += p.y; s2 += p.z; s3 += p.w;
                }
                s0 = fmaxf(s0, 0.f); s1 = fmaxf(s1, 0.f);
                s2 = fmaxf(s2, 0.f); s3 = fmaxf(s3, 0.f);
                v[f][0] = s0; v[f][1] = s1; v[f][2] = s2; v[f][3] = s3;
                r[f][0] = s0 - __bfloat162float(__float2bfloat16(s0));
                r[f][1] = s1 - __bfloat162float(__float2bfloat16(s1));
                r[f][2] = s2 - __bfloat162float(__float2bfloat16(s2));
                r[f][3] = s3 - __bfloat162float(__float2bfloat16(s3));
            }
#pragma unroll
            for (int cpair = 0; cpair < 2; ++cpair) {
                const int f = cpair * 2;
                uint4 hi4, lo4;
                hi4.x = pk(v[f][0], v[f][1]);         hi4.y = pk(v[f][2], v[f][3]);
                hi4.z = pk(v[f + 1][0], v[f + 1][1]); hi4.w = pk(v[f + 1][2], v[f + 1][3]);
                lo4.x = pk(r[f][0], r[f][1]);         lo4.y = pk(r[f][2], r[f][3]);
                lo4.z = pk(r[f + 1][0], r[f + 1][1]); lo4.w = pk(r[f + 1][2], r[f + 1][3]);
                uint4* dst = hnxt + ((size_t)(mtg * 64 + kcd + cpair) * 2) * 32 + l;
                dst[0]  = hi4;
                dst[32] = lo4;
            }
            if (t == T_ - 1) {
                int r0 = mtg * 16 + (l >> 2);
#pragma unroll
                for (int f = 0; f < 4; ++f) {
                    int c0 = n0 + f * 8 + 2 * (l & 3);
                    *(float2*)&hf[(size_t)r0 * H_ + c0]       = make_float2(v[f][0], v[f][1]);
                    *(float2*)&hf[(size_t)(r0 + 8) * H_ + c0] = make_float2(v[f][2], v[f][3]);
                }
            }
        }
        group_sync(grp);
    }

    // ---- final: out[m][o] = sum_k h[m][k] * Wo[o][k]; 2 batch rows per CTA ---
    {
        float* sw = (float*)smem;                 // [128][129] padded
        float* sh = (float*)smem + 128 * 129;     // [2][1024]
        const int m = bid * 2;
        const int half = (tid >> 7) & 1, o = tid & 127;
        for (int i = tid; i < 2 * H_; i += NTHR)
            sh[i] = hf[(size_t)(m + (i >> 10)) * H_ + (i & 1023)];
        float acc = 0.f;
        for (int k0 = 0; k0 < H_; k0 += 128) {
            __syncthreads();
            for (int i = tid; i < 128 * 128; i += NTHR) {
                int oo = i >> 7, kk = i & 127;
                sw[oo * 129 + kk] = Wo[(size_t)oo * H_ + k0 + kk];
            }
            __syncthreads();
            if (tid < 256) {
#pragma unroll 8
                for (int kk = 0; kk < 128; ++kk)
                    acc = fmaf(sh[half * H_ + k0 + kk], sw[o * 129 + kk], acc);
            }
        }
        if (tid < 256)
            out[(size_t)(m + half) * OUT_ + o] = acc;
    }
}

// ---------------- launch --------------------------------------------------
extern "C" void kernel_launch(void* const* d_in, const int* in_sizes, int n_in,
                              void* d_out, int out_size) {
    (void)in_sizes; (void)n_in; (void)out_size;
    const float* x  = (const float*)d_in[0];
    const float* Wh = (const float*)d_in[1];
    const float* Wx = (const float*)d_in[2];
    const float* Wo = (const float*)d_in[3];
    float* out = (float*)d_out;

    uint4 *phA, *pxp;
    float* phf;
    cudaGetSymbolAddress((void**)&phA, g_hA);
    cudaGetSymbolAddress((void**)&pxp, g_xp);
    cudaGetSymbolAddress((void**)&phf, g_hf);

    pack_x<<<4096, 256>>>(x, pxp);

    cudaFuncSetAttribute(rnn_mma, cudaFuncAttributeMaxDynamicSharedMemorySize, SMEM_BYTES);
    rnn_mma<<<NCTA, NTHR, SMEM_BYTES>>>(out, Wh, Wx, Wo, pxp, phA, phf);
}